// round 1
// baseline (speedup 1.0000x reference)
#include <cuda_runtime.h>

#define B_  2
#define S_  2048
#define D_  1024
#define H_  16
#define DH  64
#define ROWS (B_ * S_)        // 4096
#define TD  (3 * D_)          // 3072

// Scratch (allocation-free rule: __device__ globals)
__device__ float g_qkv[ROWS * TD];   // [4096, 3072]  q|k|v
__device__ float g_o[ROWS * D_];     // [4096, 1024]  attention output

// ---------------------------------------------------------------------------
// SGEMM: C[M,N] = A[M,K] @ B[K,N] (+ bias).  128x128 block, 8 K-slice,
// 256 threads, 8x8 per-thread micro-tile.
// ---------------------------------------------------------------------------
template<bool BIAS>
__global__ __launch_bounds__(256) void sgemm_kernel(
    const float* __restrict__ A, const float* __restrict__ Bm,
    const float* __restrict__ bias, float* __restrict__ C,
    int M, int N, int K)
{
    __shared__ __align__(16) float As[8][128];
    __shared__ __align__(16) float Bs[8][128];

    const int tid  = threadIdx.x;
    const int row0 = blockIdx.y * 128;
    const int col0 = blockIdx.x * 128;
    const int arow = tid >> 1, acol = (tid & 1) * 4;
    const int brow = tid >> 5, bcol = (tid & 31) * 4;
    const int ty = tid >> 4, tx = tid & 15;

    const float* Ap = A + (size_t)(row0 + arow) * K + acol;
    const float* Bp = Bm + (size_t)brow * N + col0 + bcol;

    float acc[8][8];
#pragma unroll
    for (int i = 0; i < 8; i++)
#pragma unroll
        for (int j = 0; j < 8; j++) acc[i][j] = 0.0f;

    for (int kb = 0; kb < K; kb += 8) {
        float4 av = *(const float4*)(Ap + kb);
        float4 bv = *(const float4*)(Bp + (size_t)kb * N);
        As[acol + 0][arow] = av.x;
        As[acol + 1][arow] = av.y;
        As[acol + 2][arow] = av.z;
        As[acol + 3][arow] = av.w;
        *(float4*)&Bs[brow][bcol] = bv;
        __syncthreads();
#pragma unroll
        for (int k = 0; k < 8; k++) {
            float4 a0 = *(const float4*)&As[k][ty * 8];
            float4 a1 = *(const float4*)&As[k][ty * 8 + 4];
            float4 b0 = *(const float4*)&Bs[k][tx * 8];
            float4 b1 = *(const float4*)&Bs[k][tx * 8 + 4];
            float af[8] = {a0.x, a0.y, a0.z, a0.w, a1.x, a1.y, a1.z, a1.w};
            float bf[8] = {b0.x, b0.y, b0.z, b0.w, b1.x, b1.y, b1.z, b1.w};
#pragma unroll
            for (int i = 0; i < 8; i++)
#pragma unroll
                for (int j = 0; j < 8; j++)
                    acc[i][j] += af[i] * bf[j];
        }
        __syncthreads();
    }

#pragma unroll
    for (int i = 0; i < 8; i++) {
        float* Cp = C + (size_t)(row0 + ty * 8 + i) * N + col0 + tx * 8;
#pragma unroll
        for (int j = 0; j < 8; j += 4) {
            float4 v;
            v.x = acc[i][j + 0]; v.y = acc[i][j + 1];
            v.z = acc[i][j + 2]; v.w = acc[i][j + 3];
            if (BIAS) {
                const float* bp = bias + col0 + tx * 8 + j;
                v.x += bp[0]; v.y += bp[1]; v.z += bp[2]; v.w += bp[3];
            }
            *(float4*)(Cp + j) = v;
        }
    }
}

// ---------------------------------------------------------------------------
// ReLU attention: per (b,h), O = relu(mask(Q Kt)) V, causal.
// One block = one 64-row q-tile. Streams 64-row k/v tiles, k-tile <= q-tile.
// Smem: Qst/Kst d-major (transposed) pad 68, Vs k-major pad 68, Ss pad 68.
// ---------------------------------------------------------------------------
#define PAD 68
#define ATTN_SMEM (4 * 64 * PAD * sizeof(float))   // 69632 B

__global__ __launch_bounds__(256) void relu_attn_kernel(
    const float* __restrict__ qkv, float* __restrict__ o)
{
    extern __shared__ __align__(16) float sm[];
    float* Qst = sm;                 // [64][PAD]  Qst[d][r]
    float* Kst = sm + 64 * PAD;      // [64][PAD]  Kst[d][c]
    float* Vs  = sm + 2 * 64 * PAD;  // [64][PAD]  Vs[k][d]
    float* Ss  = sm + 3 * 64 * PAD;  // [64][PAD]

    const int qt  = (int)gridDim.x - 1 - (int)blockIdx.x;  // heavy blocks first
    const int h   = blockIdx.y;
    const int b   = blockIdx.z;
    const int tid = threadIdx.x;
    const int ty = tid >> 4, tx = tid & 15;
    const int lr = tid >> 4;            // load row within group of 16
    const int lc = (tid & 15) * 4;      // load col (float4)

    const size_t base = ((size_t)b * S_) * TD + (size_t)h * DH;

    // Load Q tile transposed, pre-scaled by dh^-0.5 = 0.125
    {
        const float* Qg = qkv + base + (size_t)(qt * 64) * TD;
#pragma unroll
        for (int rr = 0; rr < 64; rr += 16) {
            int r = rr + lr;
            float4 v = *(const float4*)(Qg + (size_t)r * TD + lc);
            Qst[(lc + 0) * PAD + r] = v.x * 0.125f;
            Qst[(lc + 1) * PAD + r] = v.y * 0.125f;
            Qst[(lc + 2) * PAD + r] = v.z * 0.125f;
            Qst[(lc + 3) * PAD + r] = v.w * 0.125f;
        }
    }

    float accO[4][4];
#pragma unroll
    for (int i = 0; i < 4; i++)
#pragma unroll
        for (int j = 0; j < 4; j++) accO[i][j] = 0.0f;

    for (int kt = 0; kt <= qt; kt++) {
        const float* Kg = qkv + base + D_     + (size_t)(kt * 64) * TD;
        const float* Vg = qkv + base + 2 * D_ + (size_t)(kt * 64) * TD;

        __syncthreads();   // Q ready (iter 0) / prev pass2 done reading Vs,Ss
#pragma unroll
        for (int rr = 0; rr < 64; rr += 16) {
            int r = rr + lr;
            float4 kv = *(const float4*)(Kg + (size_t)r * TD + lc);
            Kst[(lc + 0) * PAD + r] = kv.x;
            Kst[(lc + 1) * PAD + r] = kv.y;
            Kst[(lc + 2) * PAD + r] = kv.z;
            Kst[(lc + 3) * PAD + r] = kv.w;
            float4 vv = *(const float4*)(Vg + (size_t)r * TD + lc);
            *(float4*)&Vs[r * PAD + lc] = vv;
        }
        __syncthreads();

        // pass 1: S[64,64] = Q Kt (4x4 per thread)
        float accS[4][4];
#pragma unroll
        for (int i = 0; i < 4; i++)
#pragma unroll
            for (int j = 0; j < 4; j++) accS[i][j] = 0.0f;

#pragma unroll 4
        for (int d = 0; d < 64; d++) {
            float4 q4 = *(const float4*)&Qst[d * PAD + ty * 4];
            float4 k4 = *(const float4*)&Kst[d * PAD + tx * 4];
            float qa[4] = {q4.x, q4.y, q4.z, q4.w};
            float ka[4] = {k4.x, k4.y, k4.z, k4.w};
#pragma unroll
            for (int i = 0; i < 4; i++)
#pragma unroll
                for (int j = 0; j < 4; j++)
                    accS[i][j] += qa[i] * ka[j];
        }

        const bool diag = (kt == qt);
#pragma unroll
        for (int i = 0; i < 4; i++) {
            int r = ty * 4 + i;
            float s0 = fmaxf(accS[i][0], 0.0f);
            float s1 = fmaxf(accS[i][1], 0.0f);
            float s2 = fmaxf(accS[i][2], 0.0f);
            float s3 = fmaxf(accS[i][3], 0.0f);
            if (diag) {
                int c = tx * 4;
                if (c + 0 > r) s0 = 0.0f;
                if (c + 1 > r) s1 = 0.0f;
                if (c + 2 > r) s2 = 0.0f;
                if (c + 3 > r) s3 = 0.0f;
            }
            float4 sv; sv.x = s0; sv.y = s1; sv.z = s2; sv.w = s3;
            *(float4*)&Ss[r * PAD + tx * 4] = sv;
        }
        __syncthreads();

        // pass 2: O += S V
#pragma unroll 4
        for (int c = 0; c < 64; c++) {
            float4 v4 = *(const float4*)&Vs[c * PAD + tx * 4];
#pragma unroll
            for (int i = 0; i < 4; i++) {
                float s = Ss[(ty * 4 + i) * PAD + c];
                accO[i][0] += s * v4.x;
                accO[i][1] += s * v4.y;
                accO[i][2] += s * v4.z;
                accO[i][3] += s * v4.w;
            }
        }
    }

    float* Og = o + ((size_t)b * S_ + (size_t)qt * 64) * D_ + (size_t)h * DH;
#pragma unroll
    for (int i = 0; i < 4; i++) {
        int r = ty * 4 + i;
        float4 v;
        v.x = accO[i][0]; v.y = accO[i][1]; v.z = accO[i][2]; v.w = accO[i][3];
        *(float4*)(Og + (size_t)r * D_ + tx * 4) = v;
    }
}

// ---------------------------------------------------------------------------
// Gated RMSNorm, in place. One block per row (1024 floats, 256 thr x float4).
// ---------------------------------------------------------------------------
__global__ __launch_bounds__(256) void rms_gate_kernel(
    float* __restrict__ o, const float* __restrict__ scale,
    const float* __restrict__ gate)
{
    const int row = blockIdx.x;
    const int tid = threadIdx.x;
    float* p = o + (size_t)row * D_;

    float4 x = ((const float4*)p)[tid];
    float ss = x.x * x.x + x.y * x.y + x.z * x.z + x.w * x.w;
#pragma unroll
    for (int off = 16; off; off >>= 1)
        ss += __shfl_xor_sync(0xffffffffu, ss, off);

    __shared__ float red[8];
    __shared__ float s_inv;
    if ((tid & 31) == 0) red[tid >> 5] = ss;
    __syncthreads();
    if (tid == 0) {
        float t = 0.0f;
#pragma unroll
        for (int i = 0; i < 8; i++) t += red[i];
        s_inv = rsqrtf(t * (1.0f / (float)D_) + 1e-7f);
    }
    __syncthreads();
    const float inv = s_inv;

    float4 sc = ((const float4*)scale)[tid];
    float4 g  = ((const float4*)gate)[tid];
    float4 r;
    r.x = sc.x * x.x * inv * (1.0f / (1.0f + expf(-g.x * x.x)));
    r.y = sc.y * x.y * inv * (1.0f / (1.0f + expf(-g.y * x.y)));
    r.z = sc.z * x.z * inv * (1.0f / (1.0f + expf(-g.z * x.z)));
    r.w = sc.w * x.w * inv * (1.0f / (1.0f + expf(-g.w * x.w)));
    ((float4*)p)[tid] = r;
}

// ---------------------------------------------------------------------------
extern "C" void kernel_launch(void* const* d_in, const int* in_sizes, int n_in,
                              void* d_out, int out_size)
{
    const float* x     = (const float*)d_in[0];
    // d_in[1] = mem_mask: causal by construction; mask*0 + relu == skip k>q. Unused.
    const float* Wqkv  = (const float*)d_in[2];
    const float* W_out = (const float*)d_in[3];
    const float* b_out = (const float*)d_in[4];
    const float* scale = (const float*)d_in[5];
    const float* gate  = (const float*)d_in[6];
    float* out = (float*)d_out;

    float *qkv = nullptr, *obuf = nullptr;
    cudaGetSymbolAddress((void**)&qkv,  g_qkv);
    cudaGetSymbolAddress((void**)&obuf, g_o);

    cudaFuncSetAttribute(relu_attn_kernel,
                         cudaFuncAttributeMaxDynamicSharedMemorySize,
                         (int)ATTN_SMEM);

    // 1) qkv = x @ Wqkv
    dim3 g1(TD / 128, ROWS / 128);
    sgemm_kernel<false><<<g1, 256>>>(x, Wqkv, nullptr, qkv, ROWS, TD, D_);

    // 2) causal ReLU attention per (b,h,q-tile)
    dim3 ga(S_ / 64, H_, B_);
    relu_attn_kernel<<<ga, 256, ATTN_SMEM>>>(qkv, obuf);

    // 3) gated RMSNorm in place
    rms_gate_kernel<<<ROWS, 256>>>(obuf, scale, gate);

    // 4) out = o @ W_out + b_out
    dim3 g2(D_ / 128, ROWS / 128);
    sgemm_kernel<true><<<g2, 256>>>(obuf, W_out, b_out, out, ROWS, D_, D_);
}

// round 6
// speedup vs baseline: 2.6248x; 2.6248x over previous
#include <cuda_runtime.h>
#include <cuda_bf16.h>
#include <cstdint>

#define B_   2
#define S_   2048
#define D_   1024
#define H_   16
#define ROWS 4096            // B_*S_
#define TD   3072            // 3*D_

// ---------------- scratch (__device__ globals; no allocs allowed) ----------
__device__ __nv_bfloat16 g_qkvh[ROWS * TD];   // qkv hi
__device__ __nv_bfloat16 g_qkvl[ROWS * TD];   // qkv lo
__device__ float         g_o[ROWS * D_];      // attention output fp32
__device__ __nv_bfloat16 g_ah[ROWS * D_];     // A hi (x, then rmsnormed o)
__device__ __nv_bfloat16 g_al[ROWS * D_];     // A lo
__device__ __nv_bfloat16 g_bh[TD * D_];       // B^T hi  [N][K]
__device__ __nv_bfloat16 g_bl[TD * D_];       // B^T lo

// ---------------- helpers (portable PTX only: sm_80+ features) -------------
__device__ __forceinline__ uint32_t smem_u32(const void* p) {
    uint32_t a;
    asm("{ .reg .u64 t; cvta.to.shared.u64 t, %1; cvt.u32.u64 %0, t; }"
        : "=r"(a) : "l"(p));
    return a;
}
__device__ __forceinline__ void cp16(uint32_t s, const void* g) {
    asm volatile("cp.async.cg.shared.global [%0], [%1], 16;" :: "r"(s), "l"(g));
}
#define CP_COMMIT()  asm volatile("cp.async.commit_group;" ::: "memory")
#define CP_WAIT0()   asm volatile("cp.async.wait_group 0;" ::: "memory")
#define CP_WAIT1()   asm volatile("cp.async.wait_group 1;" ::: "memory")

__device__ __forceinline__ void ldsm4(uint32_t* r, uint32_t a) {
    asm volatile("ldmatrix.sync.aligned.m8n8.x4.shared.b16 {%0,%1,%2,%3}, [%4];"
                 : "=r"(r[0]), "=r"(r[1]), "=r"(r[2]), "=r"(r[3]) : "r"(a));
}
__device__ __forceinline__ void ldsm2(uint32_t* r, uint32_t a) {
    asm volatile("ldmatrix.sync.aligned.m8n8.x2.shared.b16 {%0,%1}, [%2];"
                 : "=r"(r[0]), "=r"(r[1]) : "r"(a));
}
__device__ __forceinline__ void ldsm2t(uint32_t* r, uint32_t a) {
    asm volatile("ldmatrix.sync.aligned.m8n8.x2.trans.shared.b16 {%0,%1}, [%2];"
                 : "=r"(r[0]), "=r"(r[1]) : "r"(a));
}
// d += a(16x16 bf16) * b(16x8 bf16)  fp32 accum
__device__ __forceinline__ void mma_bf16(float* d, const uint32_t* a, const uint32_t* b) {
    asm volatile("mma.sync.aligned.m16n8k16.row.col.f32.bf16.bf16.f32 "
                 "{%0,%1,%2,%3}, {%4,%5,%6,%7}, {%8,%9}, {%0,%1,%2,%3};"
                 : "+f"(d[0]), "+f"(d[1]), "+f"(d[2]), "+f"(d[3])
                 : "r"(a[0]), "r"(a[1]), "r"(a[2]), "r"(a[3]), "r"(b[0]), "r"(b[1]));
}
// pack two fp32 -> bf16x2 (lo in low half)
__device__ __forceinline__ uint32_t packbf(float lo, float hi) {
    uint32_t r;
    asm("cvt.rn.bf16x2.f32 %0, %1, %2;" : "=r"(r) : "f"(hi), "f"(lo));
    return r;
}
// truncation split: hi = top-16-bits of x (exact bf16), returns hi-as-float
__device__ __forceinline__ float hi_trunc(float x) {
    return __uint_as_float(__float_as_uint(x) & 0xffff0000u);
}

// ---------------------------------------------------------------------------
// Prep: fp32 -> bf16 hi/lo (trunc hi, rn lo), packed pair writes.
// ---------------------------------------------------------------------------
__global__ __launch_bounds__(256) void split_fp32(
    const float* __restrict__ x, __nv_bfloat16* __restrict__ h,
    __nv_bfloat16* __restrict__ l, int n4)
{
    int i = blockIdx.x * 256 + threadIdx.x;
    if (i >= n4) return;
    float4 v = ((const float4*)x)[i];
    uint32_t u0 = __float_as_uint(v.x), u1 = __float_as_uint(v.y);
    uint32_t u2 = __float_as_uint(v.z), u3 = __float_as_uint(v.w);
    uint32_t* hp = (uint32_t*)h;
    uint32_t* lp = (uint32_t*)l;
    hp[2 * i]     = (u1 & 0xffff0000u) | (u0 >> 16);
    hp[2 * i + 1] = (u3 & 0xffff0000u) | (u2 >> 16);
    lp[2 * i]     = packbf(v.x - hi_trunc(v.x), v.y - hi_trunc(v.y));
    lp[2 * i + 1] = packbf(v.z - hi_trunc(v.z), v.w - hi_trunc(v.w));
}

// ---------------------------------------------------------------------------
// Prep: W[K,N] fp32 -> Bt[N,K] bf16 hi/lo (transpose + split).
// ---------------------------------------------------------------------------
__global__ __launch_bounds__(256) void transpose_split(
    const float* __restrict__ W, __nv_bfloat16* __restrict__ bh,
    __nv_bfloat16* __restrict__ bl, int K, int N)
{
    __shared__ float t[32][33];
    const int bx = blockIdx.x * 32, by = blockIdx.y * 32;
    const int tx = threadIdx.x & 31, ty = threadIdx.x >> 5;  // 32x8
#pragma unroll
    for (int i = 0; i < 32; i += 8)
        t[ty + i][tx] = W[(size_t)(by + ty + i) * N + bx + tx];
    __syncthreads();
    uint16_t* bhp = (uint16_t*)bh;
#pragma unroll
    for (int i = 0; i < 32; i += 8) {
        float v = t[tx][ty + i];
        int n = bx + ty + i, k = by + tx;
        bhp[(size_t)n * K + k] = (uint16_t)(__float_as_uint(v) >> 16);
        bl[(size_t)n * K + k] = __float2bfloat16(v - hi_trunc(v));
    }
}

// ---------------------------------------------------------------------------
// mma.sync bf16x3 GEMM:  C[M,Ntot] = A[M,K] @ Bt[Ntot,K]^T (+bias or split-out)
// Tile 128x128, Kc=32, 8 warps (2m x 4n), warp tile 64x32, double-buffered.
// smem per matrix chunk: 128 rows x 80B (64B data + 16B pad, conflict-free).
// ---------------------------------------------------------------------------
#define GM_MAT   10240                 // 128*80
#define GM_BUF   (4 * GM_MAT)          // Ah,Al,Bh,Bl
#define GM_SMEM  (2 * GM_BUF)          // 81920

template<bool SPLIT_OUT, bool BIAS>
__global__ __launch_bounds__(256) void gemm_mma(
    const __nv_bfloat16* __restrict__ Ah, const __nv_bfloat16* __restrict__ Al,
    const __nv_bfloat16* __restrict__ Bh, const __nv_bfloat16* __restrict__ Bl,
    const float* __restrict__ bias, float* __restrict__ Cf,
    __nv_bfloat16* __restrict__ Ch, __nv_bfloat16* __restrict__ Cl,
    int Ntot, int K)
{
    extern __shared__ __align__(16) char sm[];
    const uint32_t sb = smem_u32(sm);
    const int tid = threadIdx.x, lane = tid & 31, wid = tid >> 5;
    const int wm = wid >> 2, wn = wid & 3;
    const int row0 = blockIdx.y * 128, col0 = blockIdx.x * 128;
    const int NC = K >> 5;

    float acc[4][4][4];
#pragma unroll
    for (int a = 0; a < 4; a++)
#pragma unroll
        for (int bq = 0; bq < 4; bq++)
#pragma unroll
            for (int e = 0; e < 4; e++) acc[a][bq][e] = 0.0f;

    auto load_chunk = [&](int buf, int kc) {
        const uint32_t base = sb + buf * GM_BUF;
#pragma unroll
        for (int i = 0; i < 8; i++) {
            int u = i * 256 + tid;                 // 0..2047
            int mat = u >> 9;                      // compile-time per i
            int v = u & 511, r = v >> 2, c = v & 3;
            uint32_t so = base + mat * GM_MAT + r * 80 + c * 16;
            const __nv_bfloat16* src = (mat == 0) ? Ah : (mat == 1) ? Al
                                     : (mat == 2) ? Bh : Bl;
            int grow = ((mat < 2) ? row0 : col0) + r;
            cp16(so, src + (size_t)grow * K + kc * 32 + c * 8);
        }
        CP_COMMIT();
    };

    load_chunk(0, 0);

    for (int c = 0; c < NC; c++) {
        if (c + 1 < NC) { load_chunk((c + 1) & 1, c + 1); CP_WAIT1(); }
        else           { CP_WAIT0(); }
        __syncthreads();

        const uint32_t bA  = sb + (c & 1) * GM_BUF;
        const uint32_t bAl = bA + GM_MAT;
        const uint32_t bB  = bA + 2 * GM_MAT;
        const uint32_t bBl = bA + 3 * GM_MAT;
        const int l = lane & 15;
#pragma unroll
        for (int ks = 0; ks < 2; ks++) {
            const int k0 = ks * 16;
            const uint32_t aoff = (uint32_t)((lane & 15) * 80 + (k0 + (lane >> 4) * 8) * 2);
            const uint32_t boff = (uint32_t)((l & 7) * 80 + (k0 + ((l >> 3) & 1) * 8) * 2);
            uint32_t fa[4][4], fal[4][4];
#pragma unroll
            for (int mi = 0; mi < 4; mi++) {
                uint32_t r_ = (uint32_t)((wm * 64 + mi * 16) * 80);
                ldsm4(fa[mi],  bA  + r_ + aoff);
                ldsm4(fal[mi], bAl + r_ + aoff);
            }
#pragma unroll
            for (int nj = 0; nj < 4; nj++) {
                uint32_t fb[2], fbl[2];
                uint32_t r_ = (uint32_t)((wn * 32 + nj * 8) * 80);
                ldsm2(fb,  bB  + r_ + boff);
                ldsm2(fbl, bBl + r_ + boff);
#pragma unroll
                for (int mi = 0; mi < 4; mi++) {
                    mma_bf16(acc[mi][nj], fa[mi],  fb);
                    mma_bf16(acc[mi][nj], fa[mi],  fbl);
                    mma_bf16(acc[mi][nj], fal[mi], fb);
                }
            }
        }
        __syncthreads();
    }

    // -------- epilogue --------
    const int g = lane >> 2, tig = lane & 3;
#pragma unroll
    for (int mi = 0; mi < 4; mi++) {
#pragma unroll
        for (int nj = 0; nj < 4; nj++) {
            int row = row0 + wm * 64 + mi * 16 + g;
            int col = col0 + wn * 32 + nj * 8 + tig * 2;
            float c0 = acc[mi][nj][0], c1 = acc[mi][nj][1];
            float c2 = acc[mi][nj][2], c3 = acc[mi][nj][3];
            if (SPLIT_OUT) {
                uint32_t u0 = __float_as_uint(c0), u1 = __float_as_uint(c1);
                uint32_t u2 = __float_as_uint(c2), u3 = __float_as_uint(c3);
                *(uint32_t*)(Ch + (size_t)row * Ntot + col) =
                    (u1 & 0xffff0000u) | (u0 >> 16);
                *(uint32_t*)(Cl + (size_t)row * Ntot + col) =
                    packbf(c0 - hi_trunc(c0), c1 - hi_trunc(c1));
                *(uint32_t*)(Ch + (size_t)(row + 8) * Ntot + col) =
                    (u3 & 0xffff0000u) | (u2 >> 16);
                *(uint32_t*)(Cl + (size_t)(row + 8) * Ntot + col) =
                    packbf(c2 - hi_trunc(c2), c3 - hi_trunc(c3));
            } else {
                float b0 = BIAS ? bias[col] : 0.0f;
                float b1 = BIAS ? bias[col + 1] : 0.0f;
                float2 v0; v0.x = c0 + b0; v0.y = c1 + b1;
                float2 v1; v1.x = c2 + b0; v1.y = c3 + b1;
                *(float2*)(Cf + (size_t)row * Ntot + col) = v0;
                *(float2*)(Cf + (size_t)(row + 8) * Ntot + col) = v1;
            }
        }
    }
}

// ---------------------------------------------------------------------------
// ReLU attention, mma.sync bf16x3.  Block = (b, h, 64 q-rows), 4 warps.
// Warp w: q rows [16w,16w+16).  Streams 64-key tiles, kt <= qt (causal exact:
// masked logits are multiplied by 0 then relu'd -> contribute nothing).
// S accums in fp32 regs -> scale 0.125, relu, diag-mask -> split to bf16
// hi/lo A-fragments in registers (accum layout == A layout) -> S@V mmas.
// smem: Qh,Ql,Kh,Kl,Vh,Vl each 64 rows x 144B (128B data + 16B pad).
// ---------------------------------------------------------------------------
#define AT_MAT   9216                  // 64*144
#define AT_SMEM  (6 * AT_MAT)          // 55296

__global__ __launch_bounds__(128) void attn_mma(
    const __nv_bfloat16* __restrict__ qh, const __nv_bfloat16* __restrict__ ql,
    float* __restrict__ o)
{
    extern __shared__ __align__(16) char sm[];
    const uint32_t sb = smem_u32(sm);
    const uint32_t sQh = sb, sQl = sb + AT_MAT;
    const uint32_t sKV = sb + 2 * AT_MAT;   // Kh,Kl,Vh,Vl
    const int qt = (int)gridDim.x - 1 - (int)blockIdx.x;   // heavy first
    const int h = blockIdx.y, b = blockIdx.z;
    const int tid = threadIdx.x, lane = tid & 31, wid = tid >> 5;
    const int g = lane >> 2, tig = lane & 3;

    // ---- load Q tile (64 x 64 bf16 hi/lo) ----
#pragma unroll
    for (int i = 0; i < 4; i++) {
        int u = i * 128 + tid;             // 0..511
        int r = u >> 3, c = u & 7;
        uint32_t so = (uint32_t)(r * 144 + c * 16);
        size_t go = (size_t)(b * S_ + qt * 64 + r) * TD + h * 64 + c * 8;
        cp16(sQh + so, qh + go);
        cp16(sQl + so, ql + go);
    }
    CP_COMMIT();

    float accO[8][4];
#pragma unroll
    for (int nj = 0; nj < 8; nj++)
#pragma unroll
        for (int e = 0; e < 4; e++) accO[nj][e] = 0.0f;

    for (int kt = 0; kt <= qt; kt++) {
        // ---- load K/V tile ----
#pragma unroll
        for (int i = 0; i < 16; i++) {
            int u = i * 128 + tid;         // 0..2047
            int mat = u >> 9;              // 0 Kh, 1 Kl, 2 Vh, 3 Vl (const per i)
            int v = u & 511, r = v >> 3, c = v & 7;
            uint32_t so = sKV + mat * AT_MAT + (uint32_t)(r * 144 + c * 16);
            size_t grow = (size_t)(b * S_ + kt * 64 + r);
            int gcol = ((mat < 2) ? D_ : 2 * D_) + h * 64 + c * 8;
            const __nv_bfloat16* src = (mat & 1) ? ql : qh;
            cp16(so, src + grow * TD + gcol);
        }
        CP_COMMIT();
        CP_WAIT0();
        __syncthreads();

        const uint32_t sKh = sKV, sKl = sKV + AT_MAT;
        const uint32_t sVh = sKV + 2 * AT_MAT, sVl = sKV + 3 * AT_MAT;
        const int l = lane & 15;

        // ---- S = Q @ K^T  (16 x 64 per warp) ----
        float accS[8][4];
#pragma unroll
        for (int nj = 0; nj < 8; nj++)
#pragma unroll
            for (int e = 0; e < 4; e++) accS[nj][e] = 0.0f;

#pragma unroll
        for (int ks = 0; ks < 4; ks++) {
            const int k0 = ks * 16;
            const uint32_t aoff =
                (uint32_t)((wid * 16 + (lane & 15)) * 144 + (k0 + (lane >> 4) * 8) * 2);
            uint32_t fqh[4], fql[4];
            ldsm4(fqh, sQh + aoff);
            ldsm4(fql, sQl + aoff);
            const uint32_t boff =
                (uint32_t)((l & 7) * 144 + (k0 + ((l >> 3) & 1) * 8) * 2);
#pragma unroll
            for (int nj = 0; nj < 8; nj++) {
                uint32_t fkh[2], fkl[2];
                uint32_t r_ = (uint32_t)(nj * 8 * 144);
                ldsm2(fkh, sKh + r_ + boff);
                ldsm2(fkl, sKl + r_ + boff);
                mma_bf16(accS[nj], fqh, fkh);
                mma_bf16(accS[nj], fqh, fkl);
                mma_bf16(accS[nj], fql, fkh);
            }
        }

        // ---- epilogue: scale, relu, diag mask, split to A-frags ----
        const bool diag = (kt == qt);
        uint32_t sh[4][4], sl[4][4];
#pragma unroll
        for (int f = 0; f < 4; f++) {
#pragma unroll
            for (int half = 0; half < 2; half++) {
                const int nj = 2 * f + half;
                float s[4];
#pragma unroll
                for (int e = 0; e < 4; e++) {
                    float v = accS[nj][e] * 0.125f;
                    v = fmaxf(v, 0.0f);
                    if (diag) {
                        int rl = wid * 16 + g + ((e & 2) ? 8 : 0);
                        int cl = nj * 8 + tig * 2 + (e & 1);
                        if (cl > rl) v = 0.0f;
                    }
                    s[e] = v;
                }
                uint32_t u0 = __float_as_uint(s[0]), u1 = __float_as_uint(s[1]);
                uint32_t u2 = __float_as_uint(s[2]), u3 = __float_as_uint(s[3]);
                sh[f][half * 2 + 0] = (u1 & 0xffff0000u) | (u0 >> 16);
                sh[f][half * 2 + 1] = (u3 & 0xffff0000u) | (u2 >> 16);
                sl[f][half * 2 + 0] = packbf(s[0] - hi_trunc(s[0]), s[1] - hi_trunc(s[1]));
                sl[f][half * 2 + 1] = packbf(s[2] - hi_trunc(s[2]), s[3] - hi_trunc(s[3]));
            }
        }

        // ---- O += S @ V  (V via ldmatrix.trans) ----
#pragma unroll
        for (int ks = 0; ks < 4; ks++) {
            const uint32_t voff = (uint32_t)((ks * 16 + (lane & 15)) * 144);
#pragma unroll
            for (int nj = 0; nj < 8; nj++) {
                uint32_t fvh[2], fvl[2];
                uint32_t co = (uint32_t)(nj * 16);
                ldsm2t(fvh, sVh + voff + co);
                ldsm2t(fvl, sVl + voff + co);
                mma_bf16(accO[nj], sh[ks], fvh);
                mma_bf16(accO[nj], sh[ks], fvl);
                mma_bf16(accO[nj], sl[ks], fvh);
            }
        }
        __syncthreads();
    }

    // ---- store O (fp32) ----
#pragma unroll
    for (int nj = 0; nj < 8; nj++) {
        int col = h * 64 + nj * 8 + tig * 2;
        size_t row = (size_t)(b * S_ + qt * 64 + wid * 16 + g);
        float2 v0; v0.x = accO[nj][0]; v0.y = accO[nj][1];
        float2 v1; v1.x = accO[nj][2]; v1.y = accO[nj][3];
        *(float2*)(o + row * D_ + col) = v0;
        *(float2*)(o + (row + 8) * D_ + col) = v1;
    }
}

// ---------------------------------------------------------------------------
// Gated RMSNorm; reads o fp32, writes bf16 hi/lo split (A operand of GEMM2).
// ---------------------------------------------------------------------------
__global__ __launch_bounds__(256) void rms_gate_split(
    const float* __restrict__ o, const float* __restrict__ scale,
    const float* __restrict__ gate, __nv_bfloat16* __restrict__ ah,
    __nv_bfloat16* __restrict__ al)
{
    const int row = blockIdx.x;
    const int tid = threadIdx.x;
    const float* p = o + (size_t)row * D_;

    float4 x = ((const float4*)p)[tid];
    float ss = x.x * x.x + x.y * x.y + x.z * x.z + x.w * x.w;
#pragma unroll
    for (int off = 16; off; off >>= 1)
        ss += __shfl_xor_sync(0xffffffffu, ss, off);

    __shared__ float red[8];
    __shared__ float s_inv;
    if ((tid & 31) == 0) red[tid >> 5] = ss;
    __syncthreads();
    if (tid == 0) {
        float t = 0.0f;
#pragma unroll
        for (int i = 0; i < 8; i++) t += red[i];
        s_inv = rsqrtf(t * (1.0f / (float)D_) + 1e-7f);
    }
    __syncthreads();
    const float inv = s_inv;

    float4 sc = ((const float4*)scale)[tid];
    float4 gv = ((const float4*)gate)[tid];
    float r0 = sc.x * x.x * inv * (1.0f / (1.0f + expf(-gv.x * x.x)));
    float r1 = sc.y * x.y * inv * (1.0f / (1.0f + expf(-gv.y * x.y)));
    float r2 = sc.z * x.z * inv * (1.0f / (1.0f + expf(-gv.z * x.z)));
    float r3 = sc.w * x.w * inv * (1.0f / (1.0f + expf(-gv.w * x.w)));

    uint32_t u0 = __float_as_uint(r0), u1 = __float_as_uint(r1);
    uint32_t u2 = __float_as_uint(r2), u3 = __float_as_uint(r3);
    uint32_t* hp = (uint32_t*)ah;
    uint32_t* lp = (uint32_t*)al;
    const size_t base = (size_t)row * (D_ / 2) + tid * 2;
    hp[base]     = (u1 & 0xffff0000u) | (u0 >> 16);
    hp[base + 1] = (u3 & 0xffff0000u) | (u2 >> 16);
    lp[base]     = packbf(r0 - hi_trunc(r0), r1 - hi_trunc(r1));
    lp[base + 1] = packbf(r2 - hi_trunc(r2), r3 - hi_trunc(r3));
}

// ---------------------------------------------------------------------------
extern "C" void kernel_launch(void* const* d_in, const int* in_sizes, int n_in,
                              void* d_out, int out_size)
{
    const float* x     = (const float*)d_in[0];
    // d_in[1] mem_mask: causal by construction; mask*0 then relu == skip. Unused.
    const float* Wqkv  = (const float*)d_in[2];
    const float* W_out = (const float*)d_in[3];
    const float* b_out = (const float*)d_in[4];
    const float* scale = (const float*)d_in[5];
    const float* gate  = (const float*)d_in[6];
    float* out = (float*)d_out;

    float* obuf;
    __nv_bfloat16 *qkvh, *qkvl, *ah, *al, *bh, *bl;
    cudaGetSymbolAddress((void**)&obuf, g_o);
    cudaGetSymbolAddress((void**)&qkvh, g_qkvh);
    cudaGetSymbolAddress((void**)&qkvl, g_qkvl);
    cudaGetSymbolAddress((void**)&ah, g_ah);
    cudaGetSymbolAddress((void**)&al, g_al);
    cudaGetSymbolAddress((void**)&bh, g_bh);
    cudaGetSymbolAddress((void**)&bl, g_bl);

    cudaFuncSetAttribute(gemm_mma<true, false>,
                         cudaFuncAttributeMaxDynamicSharedMemorySize, GM_SMEM);
    cudaFuncSetAttribute(gemm_mma<false, true>,
                         cudaFuncAttributeMaxDynamicSharedMemorySize, GM_SMEM);
    cudaFuncSetAttribute(attn_mma,
                         cudaFuncAttributeMaxDynamicSharedMemorySize, AT_SMEM);

    // 1) split x (A of GEMM1); transpose+split Wqkv
    split_fp32<<<(ROWS * D_ / 4 + 255) / 256, 256>>>(x, ah, al, ROWS * D_ / 4);
    transpose_split<<<dim3(TD / 32, D_ / 32), 256>>>(Wqkv, bh, bl, D_, TD);

    // 2) qkv = x @ Wqkv  -> bf16 hi/lo directly (fused split)
    gemm_mma<true, false><<<dim3(TD / 128, ROWS / 128), 256, GM_SMEM>>>(
        ah, al, bh, bl, nullptr, nullptr, qkvh, qkvl, TD, D_);

    // 3) causal ReLU attention (mma bf16x3)
    attn_mma<<<dim3(S_ / 64, H_, B_), 128, AT_SMEM>>>(qkvh, qkvl, obuf);

    // 4) gated RMSNorm -> split (A of GEMM2)
    rms_gate_split<<<ROWS, 256>>>(obuf, scale, gate, ah, al);

    // 5) out = o @ W_out + b_out
    transpose_split<<<dim3(D_ / 32, D_ / 32), 256>>>(W_out, bh, bl, D_, D_);
    gemm_mma<false, true><<<dim3(D_ / 128, ROWS / 128), 256, GM_SMEM>>>(
        ah, al, bh, bl, b_out, out, nullptr, nullptr, D_, D_);
}

// round 7
// speedup vs baseline: 3.0617x; 1.1664x over previous
#include <cuda_runtime.h>
#include <cuda_bf16.h>
#include <cstdint>

#define B_   2
#define S_   2048
#define D_   1024
#define H_   16
#define ROWS 4096            // B_*S_
#define TD   3072            // 3*D_

// ---------------- scratch (__device__ globals; no allocs allowed) ----------
__device__ __nv_bfloat16 g_qkvh[ROWS * TD];   // qkv hi
__device__ __nv_bfloat16 g_qkvl[ROWS * TD];   // qkv lo
__device__ float         g_o[ROWS * D_];      // attention output fp32
__device__ __nv_bfloat16 g_ah[ROWS * D_];     // A hi (x, then rmsnormed o)
__device__ __nv_bfloat16 g_al[ROWS * D_];     // A lo
__device__ __nv_bfloat16 g_bh[TD * D_];       // B^T hi  [N][K]
__device__ __nv_bfloat16 g_bl[TD * D_];       // B^T lo

// ---------------- helpers (portable PTX only: sm_80+ features) -------------
__device__ __forceinline__ uint32_t smem_u32(const void* p) {
    uint32_t a;
    asm("{ .reg .u64 t; cvta.to.shared.u64 t, %1; cvt.u32.u64 %0, t; }"
        : "=r"(a) : "l"(p));
    return a;
}
__device__ __forceinline__ void cp16(uint32_t s, const void* g) {
    asm volatile("cp.async.cg.shared.global [%0], [%1], 16;" :: "r"(s), "l"(g));
}
#define CP_COMMIT()  asm volatile("cp.async.commit_group;" ::: "memory")
#define CP_WAIT0()   asm volatile("cp.async.wait_group 0;" ::: "memory")
#define CP_WAIT1()   asm volatile("cp.async.wait_group 1;" ::: "memory")
#define CP_WAIT2()   asm volatile("cp.async.wait_group 2;" ::: "memory")

__device__ __forceinline__ void ldsm4(uint32_t* r, uint32_t a) {
    asm volatile("ldmatrix.sync.aligned.m8n8.x4.shared.b16 {%0,%1,%2,%3}, [%4];"
                 : "=r"(r[0]), "=r"(r[1]), "=r"(r[2]), "=r"(r[3]) : "r"(a));
}
__device__ __forceinline__ void ldsm2(uint32_t* r, uint32_t a) {
    asm volatile("ldmatrix.sync.aligned.m8n8.x2.shared.b16 {%0,%1}, [%2];"
                 : "=r"(r[0]), "=r"(r[1]) : "r"(a));
}
__device__ __forceinline__ void ldsm2t(uint32_t* r, uint32_t a) {
    asm volatile("ldmatrix.sync.aligned.m8n8.x2.trans.shared.b16 {%0,%1}, [%2];"
                 : "=r"(r[0]), "=r"(r[1]) : "r"(a));
}
__device__ __forceinline__ void mma_bf16(float* d, const uint32_t* a, const uint32_t* b) {
    asm volatile("mma.sync.aligned.m16n8k16.row.col.f32.bf16.bf16.f32 "
                 "{%0,%1,%2,%3}, {%4,%5,%6,%7}, {%8,%9}, {%0,%1,%2,%3};"
                 : "+f"(d[0]), "+f"(d[1]), "+f"(d[2]), "+f"(d[3])
                 : "r"(a[0]), "r"(a[1]), "r"(a[2]), "r"(a[3]), "r"(b[0]), "r"(b[1]));
}
__device__ __forceinline__ uint32_t packbf(float lo, float hi) {
    uint32_t r;
    asm("cvt.rn.bf16x2.f32 %0, %1, %2;" : "=r"(r) : "f"(hi), "f"(lo));
    return r;
}
__device__ __forceinline__ float hi_trunc(float x) {
    return __uint_as_float(__float_as_uint(x) & 0xffff0000u);
}

// ---------------------------------------------------------------------------
// Prep: fp32 -> bf16 hi/lo (trunc hi, rn lo).
// ---------------------------------------------------------------------------
__global__ __launch_bounds__(256) void split_fp32(
    const float* __restrict__ x, __nv_bfloat16* __restrict__ h,
    __nv_bfloat16* __restrict__ l, int n4)
{
    int i = blockIdx.x * 256 + threadIdx.x;
    if (i >= n4) return;
    float4 v = ((const float4*)x)[i];
    uint32_t u0 = __float_as_uint(v.x), u1 = __float_as_uint(v.y);
    uint32_t u2 = __float_as_uint(v.z), u3 = __float_as_uint(v.w);
    uint32_t* hp = (uint32_t*)h;
    uint32_t* lp = (uint32_t*)l;
    hp[2 * i]     = (u1 & 0xffff0000u) | (u0 >> 16);
    hp[2 * i + 1] = (u3 & 0xffff0000u) | (u2 >> 16);
    lp[2 * i]     = packbf(v.x - hi_trunc(v.x), v.y - hi_trunc(v.y));
    lp[2 * i + 1] = packbf(v.z - hi_trunc(v.z), v.w - hi_trunc(v.w));
}

// ---------------------------------------------------------------------------
// Prep: W[K,N] fp32 -> Bt[N,K] bf16 hi/lo (transpose + split).
// ---------------------------------------------------------------------------
__global__ __launch_bounds__(256) void transpose_split(
    const float* __restrict__ W, __nv_bfloat16* __restrict__ bh,
    __nv_bfloat16* __restrict__ bl, int K, int N)
{
    __shared__ float t[32][33];
    const int bx = blockIdx.x * 32, by = blockIdx.y * 32;
    const int tx = threadIdx.x & 31, ty = threadIdx.x >> 5;
#pragma unroll
    for (int i = 0; i < 32; i += 8)
        t[ty + i][tx] = W[(size_t)(by + ty + i) * N + bx + tx];
    __syncthreads();
    uint16_t* bhp = (uint16_t*)bh;
#pragma unroll
    for (int i = 0; i < 32; i += 8) {
        float v = t[tx][ty + i];
        int n = bx + ty + i, k = by + tx;
        bhp[(size_t)n * K + k] = (uint16_t)(__float_as_uint(v) >> 16);
        bl[(size_t)n * K + k] = __float2bfloat16(v - hi_trunc(v));
    }
}

// ---------------------------------------------------------------------------
// mma.sync bf16x3 GEMM: 128x128 tile, Kc=32, 8 warps (2x4), warp 64x32,
// 3-stage cp.async pipeline. Unpadded 64B-row smem with XOR swizzle:
//   off(r,c16) = r*64 + ((c16 ^ ((r>>1)&3))<<4)   (conflict-free for ldsm)
// ---------------------------------------------------------------------------
#define GM_MAT    8192                 // 128 rows * 64B
#define GM_STAGE  (4 * GM_MAT)         // Ah,Al,Bh,Bl = 32KB
#define GM_SMEM   (3 * GM_STAGE)       // 98304

template<bool SPLIT_OUT, bool BIAS>
__global__ __launch_bounds__(256, 2) void gemm_mma(
    const __nv_bfloat16* __restrict__ Ah, const __nv_bfloat16* __restrict__ Al,
    const __nv_bfloat16* __restrict__ Bh, const __nv_bfloat16* __restrict__ Bl,
    const float* __restrict__ bias, float* __restrict__ Cf,
    __nv_bfloat16* __restrict__ Ch, __nv_bfloat16* __restrict__ Cl,
    int Ntot, int K)
{
    extern __shared__ __align__(16) char sm[];
    const uint32_t sb = smem_u32(sm);
    const int tid = threadIdx.x, lane = tid & 31, wid = tid >> 5;
    const int wm = wid >> 2, wn = wid & 3;
    const int row0 = blockIdx.y * 128, col0 = blockIdx.x * 128;
    const int NC = K >> 5;

    float acc[4][4][4];
#pragma unroll
    for (int a = 0; a < 4; a++)
#pragma unroll
        for (int bq = 0; bq < 4; bq++)
#pragma unroll
            for (int e = 0; e < 4; e++) acc[a][bq][e] = 0.0f;

    auto load_chunk = [&](int buf, int kc) {
        const uint32_t base = sb + buf * GM_STAGE;
#pragma unroll
        for (int i = 0; i < 8; i++) {
            int u = i * 256 + tid;                 // 0..2047
            int mat = u >> 9;
            int v = u & 511, r = v >> 2, c = v & 3;
            uint32_t so = base + mat * GM_MAT + r * 64 + ((c ^ ((r >> 1) & 3)) << 4);
            const __nv_bfloat16* src = (mat == 0) ? Ah : (mat == 1) ? Al
                                     : (mat == 2) ? Bh : Bl;
            int grow = ((mat < 2) ? row0 : col0) + r;
            cp16(so, src + (size_t)grow * K + kc * 32 + c * 8);
        }
        CP_COMMIT();
    };

    load_chunk(0, 0);
    load_chunk(1, 1);

    int buf = 0;
    for (int c = 0; c < NC; c++) {
        if (c + 2 < NC) load_chunk((buf + 2) % 3, c + 2);
        const int rem = NC - 1 - c;
        if (rem >= 2)      CP_WAIT2();
        else if (rem == 1) CP_WAIT1();
        else               CP_WAIT0();
        __syncthreads();

        const uint32_t bA  = sb + buf * GM_STAGE;
        const uint32_t bAl = bA + GM_MAT;
        const uint32_t bB  = bA + 2 * GM_MAT;
        const uint32_t bBl = bA + 3 * GM_MAT;
        const int l = lane & 15;
#pragma unroll
        for (int ks = 0; ks < 2; ks++) {
            uint32_t fa[4][4], fal[4][4];
#pragma unroll
            for (int mi = 0; mi < 4; mi++) {
                int ar = wm * 64 + mi * 16 + (lane & 15);
                int ac = 2 * ks + (lane >> 4);
                uint32_t ao = (uint32_t)(ar * 64 + ((ac ^ ((ar >> 1) & 3)) << 4));
                ldsm4(fa[mi],  bA  + ao);
                ldsm4(fal[mi], bAl + ao);
            }
#pragma unroll
            for (int nj = 0; nj < 4; nj++) {
                uint32_t fb[2], fbl[2];
                int br = wn * 32 + nj * 8 + (l & 7);
                int bc = 2 * ks + (l >> 3);
                uint32_t bo = (uint32_t)(br * 64 + ((bc ^ ((br >> 1) & 3)) << 4));
                ldsm2(fb,  bB  + bo);
                ldsm2(fbl, bBl + bo);
#pragma unroll
                for (int mi = 0; mi < 4; mi++) {
                    mma_bf16(acc[mi][nj], fa[mi],  fb);
                    mma_bf16(acc[mi][nj], fa[mi],  fbl);
                    mma_bf16(acc[mi][nj], fal[mi], fb);
                }
            }
        }
        __syncthreads();
        buf = (buf + 1) % 3;
    }

    // -------- epilogue --------
    const int g = lane >> 2, tig = lane & 3;
#pragma unroll
    for (int mi = 0; mi < 4; mi++) {
#pragma unroll
        for (int nj = 0; nj < 4; nj++) {
            int row = row0 + wm * 64 + mi * 16 + g;
            int col = col0 + wn * 32 + nj * 8 + tig * 2;
            float c0 = acc[mi][nj][0], c1 = acc[mi][nj][1];
            float c2 = acc[mi][nj][2], c3 = acc[mi][nj][3];
            if (SPLIT_OUT) {
                uint32_t u0 = __float_as_uint(c0), u1 = __float_as_uint(c1);
                uint32_t u2 = __float_as_uint(c2), u3 = __float_as_uint(c3);
                *(uint32_t*)(Ch + (size_t)row * Ntot + col) =
                    (u1 & 0xffff0000u) | (u0 >> 16);
                *(uint32_t*)(Cl + (size_t)row * Ntot + col) =
                    packbf(c0 - hi_trunc(c0), c1 - hi_trunc(c1));
                *(uint32_t*)(Ch + (size_t)(row + 8) * Ntot + col) =
                    (u3 & 0xffff0000u) | (u2 >> 16);
                *(uint32_t*)(Cl + (size_t)(row + 8) * Ntot + col) =
                    packbf(c2 - hi_trunc(c2), c3 - hi_trunc(c3));
            } else {
                float b0 = BIAS ? bias[col] : 0.0f;
                float b1 = BIAS ? bias[col + 1] : 0.0f;
                float2 v0; v0.x = c0 + b0; v0.y = c1 + b1;
                float2 v1; v1.x = c2 + b0; v1.y = c3 + b1;
                *(float2*)(Cf + (size_t)row * Ntot + col) = v0;
                *(float2*)(Cf + (size_t)(row + 8) * Ntot + col) = v1;
            }
        }
    }
}

// ---------------------------------------------------------------------------
// ReLU attention, mma bf16x3.  Block = (b, h, 128 q-rows), 8 warps, 256 thr.
// Warp w owns q rows [16w,16w+16) of the tile. K/V tiles of 64 rows stream
// double-buffered; per-warp causal skip (k-tile entirely above warp stripe
// contributes 0 after mask*0+relu -> skip).  SW128 XOR swizzle, no padding:
//   off(r,c16) = r*128 + ((c16 ^ (r&7))<<4)
// ---------------------------------------------------------------------------
#define ATQ_MAT   16384                // 128 rows * 128B
#define ATKV_MAT  8192                 // 64 rows * 128B
#define AT_STAGE  (4 * ATKV_MAT)       // Kh,Kl,Vh,Vl = 32KB
#define AT_SMEM   (2 * ATQ_MAT + 2 * AT_STAGE)   // 98304

__global__ __launch_bounds__(256, 2) void attn_mma(
    const __nv_bfloat16* __restrict__ qh, const __nv_bfloat16* __restrict__ ql,
    float* __restrict__ o)
{
    extern __shared__ __align__(16) char sm[];
    const uint32_t sb = smem_u32(sm);
    const uint32_t sQh = sb, sQl = sb + ATQ_MAT;
    const uint32_t sKV = sb + 2 * ATQ_MAT;
    const int qt = (int)gridDim.x - 1 - (int)blockIdx.x;   // heavy first
    const int h = blockIdx.y, b = blockIdx.z;
    const int tid = threadIdx.x, lane = tid & 31, wid = tid >> 5;
    const int g = lane >> 2, tig = lane & 3;
    const int KT = 2 * (qt + 1);

    // ---- Q tile loads (128 x 64 bf16 hi/lo) : group 0 ----
#pragma unroll
    for (int i = 0; i < 4; i++) {
        int u = i * 256 + tid;             // 0..1023
        int r = u >> 3, c = u & 7;
        uint32_t so = (uint32_t)(r * 128 + ((c ^ (r & 7)) << 4));
        size_t go = (size_t)(b * S_ + qt * 128 + r) * TD + h * 64 + c * 8;
        cp16(sQh + so, qh + go);
        cp16(sQl + so, ql + go);
    }
    CP_COMMIT();

    auto load_kv = [&](int buf, int kt) {
        const uint32_t base = sKV + buf * AT_STAGE;
#pragma unroll
        for (int i = 0; i < 8; i++) {
            int u = i * 256 + tid;         // 0..2047
            int mat = u >> 9;              // 0 Kh, 1 Kl, 2 Vh, 3 Vl
            int v = u & 511, r = v >> 3, c = v & 7;
            uint32_t so = base + mat * ATKV_MAT +
                          (uint32_t)(r * 128 + ((c ^ (r & 7)) << 4));
            size_t grow = (size_t)(b * S_ + kt * 64 + r);
            int gcol = ((mat < 2) ? D_ : 2 * D_) + h * 64 + c * 8;
            const __nv_bfloat16* src = (mat & 1) ? ql : qh;
            cp16(so, src + grow * TD + gcol);
        }
        CP_COMMIT();
    };

    load_kv(0, 0);           // group 1

    float accO[8][4];
#pragma unroll
    for (int nj = 0; nj < 8; nj++)
#pragma unroll
        for (int e = 0; e < 4; e++) accO[nj][e] = 0.0f;

    const int rw_lo = qt * 128 + wid * 16;       // warp's first abs q row

    for (int kt = 0; kt < KT; kt++) {
        if (kt + 1 < KT) { load_kv((kt + 1) & 1, kt + 1); CP_WAIT1(); }
        else             { CP_WAIT0(); }
        __syncthreads();

        const bool skip = (kt * 64 > rw_lo + 15);
        if (!skip) {
            const uint32_t bK = sKV + (kt & 1) * AT_STAGE;
            const uint32_t sKh = bK, sKl = bK + ATKV_MAT;
            const uint32_t sVh = bK + 2 * ATKV_MAT, sVl = bK + 3 * ATKV_MAT;
            const int l = lane & 15;

            // ---- S = Q @ K^T  (16 x 64 per warp) ----
            float accS[8][4];
#pragma unroll
            for (int nj = 0; nj < 8; nj++)
#pragma unroll
                for (int e = 0; e < 4; e++) accS[nj][e] = 0.0f;

#pragma unroll
            for (int ks = 0; ks < 4; ks++) {
                int qr = wid * 16 + (lane & 15);
                int qc = 2 * ks + (lane >> 4);
                uint32_t ao = (uint32_t)(qr * 128 + ((qc ^ (qr & 7)) << 4));
                uint32_t fqh[4], fql[4];
                ldsm4(fqh, sQh + ao);
                ldsm4(fql, sQl + ao);
#pragma unroll
                for (int nj = 0; nj < 8; nj++) {
                    int kr = nj * 8 + (l & 7);
                    int kc = 2 * ks + (l >> 3);
                    uint32_t bo = (uint32_t)(kr * 128 + ((kc ^ (kr & 7)) << 4));
                    uint32_t fkh[2], fkl[2];
                    ldsm2(fkh, sKh + bo);
                    ldsm2(fkl, sKl + bo);
                    mma_bf16(accS[nj], fqh, fkh);
                    mma_bf16(accS[nj], fqh, fkl);
                    mma_bf16(accS[nj], fql, fkh);
                }
            }

            // ---- scale, relu, causal mask, split to bf16 A-frags ----
            const bool needmask = (kt * 64 + 63 > rw_lo);
            uint32_t sh[4][4], sl[4][4];
#pragma unroll
            for (int f = 0; f < 4; f++) {
#pragma unroll
                for (int half = 0; half < 2; half++) {
                    const int nj = 2 * f + half;
                    float s[4];
#pragma unroll
                    for (int e = 0; e < 4; e++) {
                        float v = accS[nj][e] * 0.125f;
                        v = fmaxf(v, 0.0f);
                        if (needmask) {
                            int qa = rw_lo + g + ((e & 2) ? 8 : 0);
                            int ka = kt * 64 + nj * 8 + tig * 2 + (e & 1);
                            if (ka > qa) v = 0.0f;
                        }
                        s[e] = v;
                    }
                    uint32_t u0 = __float_as_uint(s[0]), u1 = __float_as_uint(s[1]);
                    uint32_t u2 = __float_as_uint(s[2]), u3 = __float_as_uint(s[3]);
                    sh[f][half * 2 + 0] = (u1 & 0xffff0000u) | (u0 >> 16);
                    sh[f][half * 2 + 1] = (u3 & 0xffff0000u) | (u2 >> 16);
                    sl[f][half * 2 + 0] = packbf(s[0] - hi_trunc(s[0]), s[1] - hi_trunc(s[1]));
                    sl[f][half * 2 + 1] = packbf(s[2] - hi_trunc(s[2]), s[3] - hi_trunc(s[3]));
                }
            }

            // ---- O += S @ V  (V via ldmatrix.trans) ----
#pragma unroll
            for (int ks = 0; ks < 4; ks++) {
                int vr = ks * 16 + (lane & 15);
                uint32_t vrow = (uint32_t)(vr * 128);
                uint32_t vsw = (uint32_t)(vr & 7);
#pragma unroll
                for (int nj = 0; nj < 8; nj++) {
                    uint32_t co = (uint32_t)(((uint32_t)nj ^ vsw) << 4);
                    uint32_t fvh[2], fvl[2];
                    ldsm2t(fvh, sVh + vrow + co);
                    ldsm2t(fvl, sVl + vrow + co);
                    mma_bf16(accO[nj], sh[ks], fvh);
                    mma_bf16(accO[nj], sh[ks], fvl);
                    mma_bf16(accO[nj], sl[ks], fvh);
                }
            }
        }
        __syncthreads();
    }

    // ---- store O (fp32) ----
#pragma unroll
    for (int nj = 0; nj < 8; nj++) {
        int col = h * 64 + nj * 8 + tig * 2;
        size_t row = (size_t)(b * S_ + qt * 128 + wid * 16 + g);
        float2 v0; v0.x = accO[nj][0]; v0.y = accO[nj][1];
        float2 v1; v1.x = accO[nj][2]; v1.y = accO[nj][3];
        *(float2*)(o + row * D_ + col) = v0;
        *(float2*)(o + (row + 8) * D_ + col) = v1;
    }
}

// ---------------------------------------------------------------------------
// Gated RMSNorm; reads o fp32, writes bf16 hi/lo split (A operand of GEMM2).
// ---------------------------------------------------------------------------
__global__ __launch_bounds__(256) void rms_gate_split(
    const float* __restrict__ o, const float* __restrict__ scale,
    const float* __restrict__ gate, __nv_bfloat16* __restrict__ ah,
    __nv_bfloat16* __restrict__ al)
{
    const int row = blockIdx.x;
    const int tid = threadIdx.x;
    const float* p = o + (size_t)row * D_;

    float4 x = ((const float4*)p)[tid];
    float ss = x.x * x.x + x.y * x.y + x.z * x.z + x.w * x.w;
#pragma unroll
    for (int off = 16; off; off >>= 1)
        ss += __shfl_xor_sync(0xffffffffu, ss, off);

    __shared__ float red[8];
    __shared__ float s_inv;
    if ((tid & 31) == 0) red[tid >> 5] = ss;
    __syncthreads();
    if (tid == 0) {
        float t = 0.0f;
#pragma unroll
        for (int i = 0; i < 8; i++) t += red[i];
        s_inv = rsqrtf(t * (1.0f / (float)D_) + 1e-7f);
    }
    __syncthreads();
    const float inv = s_inv;

    float4 sc = ((const float4*)scale)[tid];
    float4 gv = ((const float4*)gate)[tid];
    float r0 = sc.x * x.x * inv * (1.0f / (1.0f + expf(-gv.x * x.x)));
    float r1 = sc.y * x.y * inv * (1.0f / (1.0f + expf(-gv.y * x.y)));
    float r2 = sc.z * x.z * inv * (1.0f / (1.0f + expf(-gv.z * x.z)));
    float r3 = sc.w * x.w * inv * (1.0f / (1.0f + expf(-gv.w * x.w)));

    uint32_t u0 = __float_as_uint(r0), u1 = __float_as_uint(r1);
    uint32_t u2 = __float_as_uint(r2), u3 = __float_as_uint(r3);
    uint32_t* hp = (uint32_t*)ah;
    uint32_t* lp = (uint32_t*)al;
    const size_t base = (size_t)row * (D_ / 2) + tid * 2;
    hp[base]     = (u1 & 0xffff0000u) | (u0 >> 16);
    hp[base + 1] = (u3 & 0xffff0000u) | (u2 >> 16);
    lp[base]     = packbf(r0 - hi_trunc(r0), r1 - hi_trunc(r1));
    lp[base + 1] = packbf(r2 - hi_trunc(r2), r3 - hi_trunc(r3));
}

// ---------------------------------------------------------------------------
extern "C" void kernel_launch(void* const* d_in, const int* in_sizes, int n_in,
                              void* d_out, int out_size)
{
    const float* x     = (const float*)d_in[0];
    // d_in[1] mem_mask: causal by construction; mask*0 then relu == skip. Unused.
    const float* Wqkv  = (const float*)d_in[2];
    const float* W_out = (const float*)d_in[3];
    const float* b_out = (const float*)d_in[4];
    const float* scale = (const float*)d_in[5];
    const float* gate  = (const float*)d_in[6];
    float* out = (float*)d_out;

    float* obuf;
    __nv_bfloat16 *qkvh, *qkvl, *ah, *al, *bh, *bl;
    cudaGetSymbolAddress((void**)&obuf, g_o);
    cudaGetSymbolAddress((void**)&qkvh, g_qkvh);
    cudaGetSymbolAddress((void**)&qkvl, g_qkvl);
    cudaGetSymbolAddress((void**)&ah, g_ah);
    cudaGetSymbolAddress((void**)&al, g_al);
    cudaGetSymbolAddress((void**)&bh, g_bh);
    cudaGetSymbolAddress((void**)&bl, g_bl);

    cudaFuncSetAttribute(gemm_mma<true, false>,
                         cudaFuncAttributeMaxDynamicSharedMemorySize, GM_SMEM);
    cudaFuncSetAttribute(gemm_mma<false, true>,
                         cudaFuncAttributeMaxDynamicSharedMemorySize, GM_SMEM);
    cudaFuncSetAttribute(attn_mma,
                         cudaFuncAttributeMaxDynamicSharedMemorySize, AT_SMEM);

    // 1) split x (A of GEMM1); transpose+split Wqkv
    split_fp32<<<(ROWS * D_ / 4 + 255) / 256, 256>>>(x, ah, al, ROWS * D_ / 4);
    transpose_split<<<dim3(TD / 32, D_ / 32), 256>>>(Wqkv, bh, bl, D_, TD);

    // 2) qkv = x @ Wqkv  -> bf16 hi/lo directly (fused split)
    gemm_mma<true, false><<<dim3(TD / 128, ROWS / 128), 256, GM_SMEM>>>(
        ah, al, bh, bl, nullptr, nullptr, qkvh, qkvl, TD, D_);

    // 3) causal ReLU attention (mma bf16x3, 128-row q-tiles, dbl-buffered)
    attn_mma<<<dim3(S_ / 128, H_, B_), 256, AT_SMEM>>>(qkvh, qkvl, obuf);

    // 4) gated RMSNorm -> split (A of GEMM2)
    rms_gate_split<<<ROWS, 256>>>(obuf, scale, gate, ah, al);

    // 5) out = o @ W_out + b_out
    transpose_split<<<dim3(D_ / 32, D_ / 32), 256>>>(W_out, bh, bl, D_, D_);
    gemm_mma<false, true><<<dim3(D_ / 128, ROWS / 128), 256, GM_SMEM>>>(
        ah, al, bh, bl, b_out, out, nullptr, nullptr, D_, D_);
}

// round 8
// speedup vs baseline: 3.0658x; 1.0013x over previous
#include <cuda_runtime.h>
#include <cuda_bf16.h>
#include <cstdint>

#define B_   2
#define S_   2048
#define D_   1024
#define H_   16
#define ROWS 4096            // B_*S_
#define TD   3072            // 3*D_

// ---------------- scratch (__device__ globals; no allocs allowed) ----------
__device__ __nv_bfloat16 g_qkvh[ROWS * TD];   // qkv hi
__device__ __nv_bfloat16 g_qkvl[ROWS * TD];   // qkv lo
__device__ float         g_o[ROWS * D_];      // attention output fp32
__device__ __nv_bfloat16 g_ah[ROWS * D_];     // A hi (x, then rmsnormed o)
__device__ __nv_bfloat16 g_al[ROWS * D_];     // A lo
__device__ __nv_bfloat16 g_bh[TD * D_];       // B^T hi  [N][K]
__device__ __nv_bfloat16 g_bl[TD * D_];       // B^T lo

// ---------------- helpers (portable PTX only: sm_80+ features) -------------
__device__ __forceinline__ uint32_t smem_u32(const void* p) {
    uint32_t a;
    asm("{ .reg .u64 t; cvta.to.shared.u64 t, %1; cvt.u32.u64 %0, t; }"
        : "=r"(a) : "l"(p));
    return a;
}
__device__ __forceinline__ void cp16(uint32_t s, const void* g) {
    asm volatile("cp.async.cg.shared.global [%0], [%1], 16;" :: "r"(s), "l"(g));
}
#define CP_COMMIT()  asm volatile("cp.async.commit_group;" ::: "memory")
#define CP_WAIT0()   asm volatile("cp.async.wait_group 0;" ::: "memory")
#define CP_WAIT1()   asm volatile("cp.async.wait_group 1;" ::: "memory")
#define CP_WAIT2()   asm volatile("cp.async.wait_group 2;" ::: "memory")

__device__ __forceinline__ void ldsm4(uint32_t* r, uint32_t a) {
    asm volatile("ldmatrix.sync.aligned.m8n8.x4.shared.b16 {%0,%1,%2,%3}, [%4];"
                 : "=r"(r[0]), "=r"(r[1]), "=r"(r[2]), "=r"(r[3]) : "r"(a));
}
__device__ __forceinline__ void ldsm4t(uint32_t* r, uint32_t a) {
    asm volatile("ldmatrix.sync.aligned.m8n8.x4.trans.shared.b16 {%0,%1,%2,%3}, [%4];"
                 : "=r"(r[0]), "=r"(r[1]), "=r"(r[2]), "=r"(r[3]) : "r"(a));
}
__device__ __forceinline__ void mma_bf16(float* d, const uint32_t* a, const uint32_t* b) {
    asm volatile("mma.sync.aligned.m16n8k16.row.col.f32.bf16.bf16.f32 "
                 "{%0,%1,%2,%3}, {%4,%5,%6,%7}, {%8,%9}, {%0,%1,%2,%3};"
                 : "+f"(d[0]), "+f"(d[1]), "+f"(d[2]), "+f"(d[3])
                 : "r"(a[0]), "r"(a[1]), "r"(a[2]), "r"(a[3]), "r"(b[0]), "r"(b[1]));
}
__device__ __forceinline__ uint32_t packbf(float lo, float hi) {
    uint32_t r;
    asm("cvt.rn.bf16x2.f32 %0, %1, %2;" : "=r"(r) : "f"(hi), "f"(lo));
    return r;
}
__device__ __forceinline__ float hi_trunc(float x) {
    return __uint_as_float(__float_as_uint(x) & 0xffff0000u);
}

// ---------------------------------------------------------------------------
// Prep: fp32 -> bf16 hi/lo (trunc hi, rn lo).
// ---------------------------------------------------------------------------
__global__ __launch_bounds__(256) void split_fp32(
    const float* __restrict__ x, __nv_bfloat16* __restrict__ h,
    __nv_bfloat16* __restrict__ l, int n4)
{
    int i = blockIdx.x * 256 + threadIdx.x;
    if (i >= n4) return;
    float4 v = ((const float4*)x)[i];
    uint32_t u0 = __float_as_uint(v.x), u1 = __float_as_uint(v.y);
    uint32_t u2 = __float_as_uint(v.z), u3 = __float_as_uint(v.w);
    uint32_t* hp = (uint32_t*)h;
    uint32_t* lp = (uint32_t*)l;
    hp[2 * i]     = (u1 & 0xffff0000u) | (u0 >> 16);
    hp[2 * i + 1] = (u3 & 0xffff0000u) | (u2 >> 16);
    lp[2 * i]     = packbf(v.x - hi_trunc(v.x), v.y - hi_trunc(v.y));
    lp[2 * i + 1] = packbf(v.z - hi_trunc(v.z), v.w - hi_trunc(v.w));
}

// ---------------------------------------------------------------------------
// Prep: W[K,N] fp32 -> Bt[N,K] bf16 hi/lo (transpose + split).
// ---------------------------------------------------------------------------
__global__ __launch_bounds__(256) void transpose_split(
    const float* __restrict__ W, __nv_bfloat16* __restrict__ bh,
    __nv_bfloat16* __restrict__ bl, int K, int N)
{
    __shared__ float t[32][33];
    const int bx = blockIdx.x * 32, by = blockIdx.y * 32;
    const int tx = threadIdx.x & 31, ty = threadIdx.x >> 5;
#pragma unroll
    for (int i = 0; i < 32; i += 8)
        t[ty + i][tx] = W[(size_t)(by + ty + i) * N + bx + tx];
    __syncthreads();
    uint16_t* bhp = (uint16_t*)bh;
#pragma unroll
    for (int i = 0; i < 32; i += 8) {
        float v = t[tx][ty + i];
        int n = bx + ty + i, k = by + tx;
        bhp[(size_t)n * K + k] = (uint16_t)(__float_as_uint(v) >> 16);
        bl[(size_t)n * K + k] = __float2bfloat16(v - hi_trunc(v));
    }
}

// ---------------------------------------------------------------------------
// mma.sync bf16x3 GEMM: 128x128 tile, Kc=32, 8 warps (2x4), warp 64x32,
// 3-stage cp.async pipeline.  Swizzle: off(r,c16) = r*64 + ((c16^((r>>1)&3))<<4)
// B-frags loaded pairwise with ldsm4 (two nj per instruction).
// ---------------------------------------------------------------------------
#define GM_MAT    8192                 // 128 rows * 64B
#define GM_STAGE  (4 * GM_MAT)         // Ah,Al,Bh,Bl = 32KB
#define GM_SMEM   (3 * GM_STAGE)       // 98304

template<bool SPLIT_OUT, bool BIAS>
__global__ __launch_bounds__(256, 2) void gemm_mma(
    const __nv_bfloat16* __restrict__ Ah, const __nv_bfloat16* __restrict__ Al,
    const __nv_bfloat16* __restrict__ Bh, const __nv_bfloat16* __restrict__ Bl,
    const float* __restrict__ bias, float* __restrict__ Cf,
    __nv_bfloat16* __restrict__ Ch, __nv_bfloat16* __restrict__ Cl,
    int Ntot, int K)
{
    extern __shared__ __align__(16) char sm[];
    const uint32_t sb = smem_u32(sm);
    const int tid = threadIdx.x, lane = tid & 31, wid = tid >> 5;
    const int wm = wid >> 2, wn = wid & 3;
    const int row0 = blockIdx.y * 128, col0 = blockIdx.x * 128;
    const int NC = K >> 5;

    float acc[4][4][4];
#pragma unroll
    for (int a = 0; a < 4; a++)
#pragma unroll
        for (int bq = 0; bq < 4; bq++)
#pragma unroll
            for (int e = 0; e < 4; e++) acc[a][bq][e] = 0.0f;

    auto load_chunk = [&](int buf, int kc) {
        const uint32_t base = sb + buf * GM_STAGE;
#pragma unroll
        for (int i = 0; i < 8; i++) {
            int u = i * 256 + tid;                 // 0..2047
            int mat = u >> 9;
            int v = u & 511, r = v >> 2, c = v & 3;
            uint32_t so = base + mat * GM_MAT + r * 64 + ((c ^ ((r >> 1) & 3)) << 4);
            const __nv_bfloat16* src = (mat == 0) ? Ah : (mat == 1) ? Al
                                     : (mat == 2) ? Bh : Bl;
            int grow = ((mat < 2) ? row0 : col0) + r;
            cp16(so, src + (size_t)grow * K + kc * 32 + c * 8);
        }
        CP_COMMIT();
    };

    load_chunk(0, 0);
    load_chunk(1, 1);

    int buf = 0;
    for (int c = 0; c < NC; c++) {
        if (c + 2 < NC) load_chunk((buf + 2) % 3, c + 2);
        const int rem = NC - 1 - c;
        if (rem >= 2)      CP_WAIT2();
        else if (rem == 1) CP_WAIT1();
        else               CP_WAIT0();
        __syncthreads();

        const uint32_t bA  = sb + buf * GM_STAGE;
        const uint32_t bAl = bA + GM_MAT;
        const uint32_t bB  = bA + 2 * GM_MAT;
        const uint32_t bBl = bA + 3 * GM_MAT;
#pragma unroll
        for (int ks = 0; ks < 2; ks++) {
            uint32_t fa[4][4], fal[4][4];
#pragma unroll
            for (int mi = 0; mi < 4; mi++) {
                int ar = wm * 64 + mi * 16 + (lane & 15);
                int ac = 2 * ks + (lane >> 4);
                uint32_t ao = (uint32_t)(ar * 64 + ((ac ^ ((ar >> 1) & 3)) << 4));
                ldsm4(fa[mi],  bA  + ao);
                ldsm4(fal[mi], bAl + ao);
            }
            // B frags: ldsm4 covers two nj per load
            //   group g = lane>>3: nj_off = g>>1, kc_off = g&1
            const int bg = lane >> 3;
            const int br_base = wn * 32 + (bg >> 1) * 8 + (lane & 7);
            const int bc = 2 * ks + (bg & 1);
#pragma unroll
            for (int nj2 = 0; nj2 < 2; nj2++) {
                int br = br_base + nj2 * 16;
                uint32_t bo = (uint32_t)(br * 64 + ((bc ^ ((br >> 1) & 3)) << 4));
                uint32_t fb[4], fbl[4];
                ldsm4(fb,  bB  + bo);
                ldsm4(fbl, bBl + bo);
#pragma unroll
                for (int half = 0; half < 2; half++) {
                    const int nj = 2 * nj2 + half;
#pragma unroll
                    for (int mi = 0; mi < 4; mi++) {
                        mma_bf16(acc[mi][nj], fa[mi],  fb  + 2 * half);
                        mma_bf16(acc[mi][nj], fa[mi],  fbl + 2 * half);
                        mma_bf16(acc[mi][nj], fal[mi], fb  + 2 * half);
                    }
                }
            }
        }
        __syncthreads();
        buf = (buf + 1) % 3;
    }

    // -------- epilogue --------
    const int g = lane >> 2, tig = lane & 3;
#pragma unroll
    for (int mi = 0; mi < 4; mi++) {
#pragma unroll
        for (int nj = 0; nj < 4; nj++) {
            int row = row0 + wm * 64 + mi * 16 + g;
            int col = col0 + wn * 32 + nj * 8 + tig * 2;
            float c0 = acc[mi][nj][0], c1 = acc[mi][nj][1];
            float c2 = acc[mi][nj][2], c3 = acc[mi][nj][3];
            if (SPLIT_OUT) {
                uint32_t u0 = __float_as_uint(c0), u1 = __float_as_uint(c1);
                uint32_t u2 = __float_as_uint(c2), u3 = __float_as_uint(c3);
                *(uint32_t*)(Ch + (size_t)row * Ntot + col) =
                    (u1 & 0xffff0000u) | (u0 >> 16);
                *(uint32_t*)(Cl + (size_t)row * Ntot + col) =
                    packbf(c0 - hi_trunc(c0), c1 - hi_trunc(c1));
                *(uint32_t*)(Ch + (size_t)(row + 8) * Ntot + col) =
                    (u3 & 0xffff0000u) | (u2 >> 16);
                *(uint32_t*)(Cl + (size_t)(row + 8) * Ntot + col) =
                    packbf(c2 - hi_trunc(c2), c3 - hi_trunc(c3));
            } else {
                float b0 = BIAS ? bias[col] : 0.0f;
                float b1 = BIAS ? bias[col + 1] : 0.0f;
                float2 v0; v0.x = c0 + b0; v0.y = c1 + b1;
                float2 v1; v1.x = c2 + b0; v1.y = c3 + b1;
                *(float2*)(Cf + (size_t)row * Ntot + col) = v0;
                *(float2*)(Cf + (size_t)(row + 8) * Ntot + col) = v1;
            }
        }
    }
}

// ---------------------------------------------------------------------------
// ReLU attention, mma bf16x3.  Block = (b, h, 128 q-rows), 8 warps.
// K/V 64-row tiles double-buffered.  K and V frags loaded pairwise (ldsm4 /
// ldsm4.trans: two nj per instruction).  Swizzle off(r,c16)=r*128+((c^(r&7))<<4)
// ---------------------------------------------------------------------------
#define ATQ_MAT   16384                // 128 rows * 128B
#define ATKV_MAT  8192                 // 64 rows * 128B
#define AT_STAGE  (4 * ATKV_MAT)       // Kh,Kl,Vh,Vl = 32KB
#define AT_SMEM   (2 * ATQ_MAT + 2 * AT_STAGE)   // 98304

__global__ __launch_bounds__(256, 2) void attn_mma(
    const __nv_bfloat16* __restrict__ qh, const __nv_bfloat16* __restrict__ ql,
    float* __restrict__ o)
{
    extern __shared__ __align__(16) char sm[];
    const uint32_t sb = smem_u32(sm);
    const uint32_t sQh = sb, sQl = sb + ATQ_MAT;
    const uint32_t sKV = sb + 2 * ATQ_MAT;
    const int qt = (int)gridDim.x - 1 - (int)blockIdx.x;   // heavy first
    const int h = blockIdx.y, b = blockIdx.z;
    const int tid = threadIdx.x, lane = tid & 31, wid = tid >> 5;
    const int g = lane >> 2, tig = lane & 3;
    const int KT = 2 * (qt + 1);

    // ---- Q tile loads (128 x 64 bf16 hi/lo) : group 0 ----
#pragma unroll
    for (int i = 0; i < 4; i++) {
        int u = i * 256 + tid;             // 0..1023
        int r = u >> 3, c = u & 7;
        uint32_t so = (uint32_t)(r * 128 + ((c ^ (r & 7)) << 4));
        size_t go = (size_t)(b * S_ + qt * 128 + r) * TD + h * 64 + c * 8;
        cp16(sQh + so, qh + go);
        cp16(sQl + so, ql + go);
    }
    CP_COMMIT();

    auto load_kv = [&](int buf, int kt) {
        const uint32_t base = sKV + buf * AT_STAGE;
#pragma unroll
        for (int i = 0; i < 8; i++) {
            int u = i * 256 + tid;         // 0..2047
            int mat = u >> 9;              // 0 Kh, 1 Kl, 2 Vh, 3 Vl
            int v = u & 511, r = v >> 3, c = v & 7;
            uint32_t so = base + mat * ATKV_MAT +
                          (uint32_t)(r * 128 + ((c ^ (r & 7)) << 4));
            size_t grow = (size_t)(b * S_ + kt * 64 + r);
            int gcol = ((mat < 2) ? D_ : 2 * D_) + h * 64 + c * 8;
            const __nv_bfloat16* src = (mat & 1) ? ql : qh;
            cp16(so, src + grow * TD + gcol);
        }
        CP_COMMIT();
    };

    load_kv(0, 0);           // group 1

    float accO[8][4];
#pragma unroll
    for (int nj = 0; nj < 8; nj++)
#pragma unroll
        for (int e = 0; e < 4; e++) accO[nj][e] = 0.0f;

    const int rw_lo = qt * 128 + wid * 16;       // warp's first abs q row

    for (int kt = 0; kt < KT; kt++) {
        if (kt + 1 < KT) { load_kv((kt + 1) & 1, kt + 1); CP_WAIT1(); }
        else             { CP_WAIT0(); }
        __syncthreads();

        const bool skip = (kt * 64 > rw_lo + 15);
        if (!skip) {
            const uint32_t bK = sKV + (kt & 1) * AT_STAGE;
            const uint32_t sKh = bK, sKl = bK + ATKV_MAT;
            const uint32_t sVh = bK + 2 * ATKV_MAT, sVl = bK + 3 * ATKV_MAT;

            // ---- S = Q @ K^T  (16 x 64 per warp) ----
            float accS[8][4];
#pragma unroll
            for (int nj = 0; nj < 8; nj++)
#pragma unroll
                for (int e = 0; e < 4; e++) accS[nj][e] = 0.0f;

            const int kg = lane >> 3;                 // 0..3
            const int kr_base = (kg >> 1) * 8 + (lane & 7);
#pragma unroll
            for (int ks = 0; ks < 4; ks++) {
                int qr = wid * 16 + (lane & 15);
                int qc = 2 * ks + (lane >> 4);
                uint32_t ao = (uint32_t)(qr * 128 + ((qc ^ (qr & 7)) << 4));
                uint32_t fqh[4], fql[4];
                ldsm4(fqh, sQh + ao);
                ldsm4(fql, sQl + ao);
                const int kc = 2 * ks + (kg & 1);
#pragma unroll
                for (int nj2 = 0; nj2 < 4; nj2++) {
                    int kr = nj2 * 16 + kr_base;
                    uint32_t bo = (uint32_t)(kr * 128 + ((kc ^ (kr & 7)) << 4));
                    uint32_t fkh[4], fkl[4];
                    ldsm4(fkh, sKh + bo);
                    ldsm4(fkl, sKl + bo);
#pragma unroll
                    for (int half = 0; half < 2; half++) {
                        const int nj = 2 * nj2 + half;
                        mma_bf16(accS[nj], fqh, fkh + 2 * half);
                        mma_bf16(accS[nj], fqh, fkl + 2 * half);
                        mma_bf16(accS[nj], fql, fkh + 2 * half);
                    }
                }
            }

            // ---- scale, relu, causal mask, split to bf16 A-frags ----
            const bool needmask = (kt * 64 + 63 > rw_lo);
            uint32_t sh[4][4], sl[4][4];
#pragma unroll
            for (int f = 0; f < 4; f++) {
#pragma unroll
                for (int half = 0; half < 2; half++) {
                    const int nj = 2 * f + half;
                    float s[4];
#pragma unroll
                    for (int e = 0; e < 4; e++) {
                        float v = accS[nj][e] * 0.125f;
                        v = fmaxf(v, 0.0f);
                        if (needmask) {
                            int qa = rw_lo + g + ((e & 2) ? 8 : 0);
                            int ka = kt * 64 + nj * 8 + tig * 2 + (e & 1);
                            if (ka > qa) v = 0.0f;
                        }
                        s[e] = v;
                    }
                    uint32_t u0 = __float_as_uint(s[0]), u1 = __float_as_uint(s[1]);
                    uint32_t u2 = __float_as_uint(s[2]), u3 = __float_as_uint(s[3]);
                    sh[f][half * 2 + 0] = (u1 & 0xffff0000u) | (u0 >> 16);
                    sh[f][half * 2 + 1] = (u3 & 0xffff0000u) | (u2 >> 16);
                    sl[f][half * 2 + 0] = packbf(s[0] - hi_trunc(s[0]), s[1] - hi_trunc(s[1]));
                    sl[f][half * 2 + 1] = packbf(s[2] - hi_trunc(s[2]), s[3] - hi_trunc(s[3]));
                }
            }

            // ---- O += S @ V  (V via ldmatrix.x4.trans: two nj per load) ----
#pragma unroll
            for (int ks = 0; ks < 4; ks++) {
                int vr = ks * 16 + ((lane >> 3) & 1) * 8 + (lane & 7);
                uint32_t vrow = (uint32_t)(vr * 128);
                uint32_t vsw = (uint32_t)(vr & 7);
                const int vcg = lane >> 4;            // col within pair
#pragma unroll
                for (int nj2 = 0; nj2 < 4; nj2++) {
                    uint32_t co = (uint32_t)(((uint32_t)(2 * nj2 + vcg) ^ vsw) << 4);
                    uint32_t fvh[4], fvl[4];
                    ldsm4t(fvh, sVh + vrow + co);
                    ldsm4t(fvl, sVl + vrow + co);
#pragma unroll
                    for (int half = 0; half < 2; half++) {
                        const int nj = 2 * nj2 + half;
                        mma_bf16(accO[nj], sh[ks], fvh + 2 * half);
                        mma_bf16(accO[nj], sh[ks], fvl + 2 * half);
                        mma_bf16(accO[nj], sl[ks], fvh + 2 * half);
                    }
                }
            }
        }
        __syncthreads();
    }

    // ---- store O (fp32) ----
#pragma unroll
    for (int nj = 0; nj < 8; nj++) {
        int col = h * 64 + nj * 8 + tig * 2;
        size_t row = (size_t)(b * S_ + qt * 128 + wid * 16 + g);
        float2 v0; v0.x = accO[nj][0]; v0.y = accO[nj][1];
        float2 v1; v1.x = accO[nj][2]; v1.y = accO[nj][3];
        *(float2*)(o + row * D_ + col) = v0;
        *(float2*)(o + (row + 8) * D_ + col) = v1;
    }
}

// ---------------------------------------------------------------------------
// Gated RMSNorm; reads o fp32, writes bf16 hi/lo split (A operand of GEMM2).
// ---------------------------------------------------------------------------
__global__ __launch_bounds__(256) void rms_gate_split(
    const float* __restrict__ o, const float* __restrict__ scale,
    const float* __restrict__ gate, __nv_bfloat16* __restrict__ ah,
    __nv_bfloat16* __restrict__ al)
{
    const int row = blockIdx.x;
    const int tid = threadIdx.x;
    const float* p = o + (size_t)row * D_;

    float4 x = ((const float4*)p)[tid];
    float ss = x.x * x.x + x.y * x.y + x.z * x.z + x.w * x.w;
#pragma unroll
    for (int off = 16; off; off >>= 1)
        ss += __shfl_xor_sync(0xffffffffu, ss, off);

    __shared__ float red[8];
    __shared__ float s_inv;
    if ((tid & 31) == 0) red[tid >> 5] = ss;
    __syncthreads();
    if (tid == 0) {
        float t = 0.0f;
#pragma unroll
        for (int i = 0; i < 8; i++) t += red[i];
        s_inv = rsqrtf(t * (1.0f / (float)D_) + 1e-7f);
    }
    __syncthreads();
    const float inv = s_inv;

    float4 sc = ((const float4*)scale)[tid];
    float4 gv = ((const float4*)gate)[tid];
    float r0 = sc.x * x.x * inv * (1.0f / (1.0f + expf(-gv.x * x.x)));
    float r1 = sc.y * x.y * inv * (1.0f / (1.0f + expf(-gv.y * x.y)));
    float r2 = sc.z * x.z * inv * (1.0f / (1.0f + expf(-gv.z * x.z)));
    float r3 = sc.w * x.w * inv * (1.0f / (1.0f + expf(-gv.w * x.w)));

    uint32_t u0 = __float_as_uint(r0), u1 = __float_as_uint(r1);
    uint32_t u2 = __float_as_uint(r2), u3 = __float_as_uint(r3);
    uint32_t* hp = (uint32_t*)ah;
    uint32_t* lp = (uint32_t*)al;
    const size_t base = (size_t)row * (D_ / 2) + tid * 2;
    hp[base]     = (u1 & 0xffff0000u) | (u0 >> 16);
    hp[base + 1] = (u3 & 0xffff0000u) | (u2 >> 16);
    lp[base]     = packbf(r0 - hi_trunc(r0), r1 - hi_trunc(r1));
    lp[base + 1] = packbf(r2 - hi_trunc(r2), r3 - hi_trunc(r3));
}

// ---------------------------------------------------------------------------
extern "C" void kernel_launch(void* const* d_in, const int* in_sizes, int n_in,
                              void* d_out, int out_size)
{
    const float* x     = (const float*)d_in[0];
    // d_in[1] mem_mask: causal by construction; mask*0 then relu == skip. Unused.
    const float* Wqkv  = (const float*)d_in[2];
    const float* W_out = (const float*)d_in[3];
    const float* b_out = (const float*)d_in[4];
    const float* scale = (const float*)d_in[5];
    const float* gate  = (const float*)d_in[6];
    float* out = (float*)d_out;

    float* obuf;
    __nv_bfloat16 *qkvh, *qkvl, *ah, *al, *bh, *bl;
    cudaGetSymbolAddress((void**)&obuf, g_o);
    cudaGetSymbolAddress((void**)&qkvh, g_qkvh);
    cudaGetSymbolAddress((void**)&qkvl, g_qkvl);
    cudaGetSymbolAddress((void**)&ah, g_ah);
    cudaGetSymbolAddress((void**)&al, g_al);
    cudaGetSymbolAddress((void**)&bh, g_bh);
    cudaGetSymbolAddress((void**)&bl, g_bl);

    cudaFuncSetAttribute(gemm_mma<true, false>,
                         cudaFuncAttributeMaxDynamicSharedMemorySize, GM_SMEM);
    cudaFuncSetAttribute(gemm_mma<false, true>,
                         cudaFuncAttributeMaxDynamicSharedMemorySize, GM_SMEM);
    cudaFuncSetAttribute(attn_mma,
                         cudaFuncAttributeMaxDynamicSharedMemorySize, AT_SMEM);

    // 1) split x (A of GEMM1); transpose+split Wqkv
    split_fp32<<<(ROWS * D_ / 4 + 255) / 256, 256>>>(x, ah, al, ROWS * D_ / 4);
    transpose_split<<<dim3(TD / 32, D_ / 32), 256>>>(Wqkv, bh, bl, D_, TD);

    // 2) qkv = x @ Wqkv  -> bf16 hi/lo directly (fused split)
    gemm_mma<true, false><<<dim3(TD / 128, ROWS / 128), 256, GM_SMEM>>>(
        ah, al, bh, bl, nullptr, nullptr, qkvh, qkvl, TD, D_);

    // 3) causal ReLU attention (mma bf16x3, ldsm4 pairwise K/V frags)
    attn_mma<<<dim3(S_ / 128, H_, B_), 256, AT_SMEM>>>(qkvh, qkvl, obuf);

    // 4) gated RMSNorm -> split (A of GEMM2)
    rms_gate_split<<<ROWS, 256>>>(obuf, scale, gate, ah, al);

    // 5) out = o @ W_out + b_out
    transpose_split<<<dim3(D_ / 32, D_ / 32), 256>>>(W_out, bh, bl, D_, D_);
    gemm_mma<false, true><<<dim3(D_ / 128, ROWS / 128), 256, GM_SMEM>>>(
        ah, al, bh, bl, b_out, out, nullptr, nullptr, D_, D_);
}

// round 9
// speedup vs baseline: 3.1765x; 1.0361x over previous
#include <cuda_runtime.h>
#include <cuda_bf16.h>
#include <cstdint>

#define B_   2
#define S_   2048
#define D_   1024
#define H_   16
#define ROWS 4096            // B_*S_
#define TD   3072            // 3*D_

// ---------------- scratch (__device__ globals; no allocs allowed) ----------
__device__ __nv_bfloat16 g_qkvh[ROWS * TD];   // qkv hi
__device__ __nv_bfloat16 g_qkvl[ROWS * TD];   // qkv lo
__device__ float         g_o[ROWS * D_];      // attention output fp32
__device__ __nv_bfloat16 g_ah[ROWS * D_];     // A hi (x, then rmsnormed o)
__device__ __nv_bfloat16 g_al[ROWS * D_];     // A lo
__device__ __nv_bfloat16 g_bh[TD * D_];       // B^T hi  [N][K]
__device__ __nv_bfloat16 g_bl[TD * D_];       // B^T lo

// ---------------- helpers (portable PTX only: sm_80+ features) -------------
__device__ __forceinline__ uint32_t smem_u32(const void* p) {
    uint32_t a;
    asm("{ .reg .u64 t; cvta.to.shared.u64 t, %1; cvt.u32.u64 %0, t; }"
        : "=r"(a) : "l"(p));
    return a;
}
__device__ __forceinline__ void cp16(uint32_t s, const void* g) {
    asm volatile("cp.async.cg.shared.global [%0], [%1], 16;" :: "r"(s), "l"(g));
}
#define CP_COMMIT()  asm volatile("cp.async.commit_group;" ::: "memory")
#define CP_WAIT0()   asm volatile("cp.async.wait_group 0;" ::: "memory")
#define CP_WAIT1()   asm volatile("cp.async.wait_group 1;" ::: "memory")
#define CP_WAIT2()   asm volatile("cp.async.wait_group 2;" ::: "memory")

__device__ __forceinline__ void ldsm4(uint32_t* r, uint32_t a) {
    asm volatile("ldmatrix.sync.aligned.m8n8.x4.shared.b16 {%0,%1,%2,%3}, [%4];"
                 : "=r"(r[0]), "=r"(r[1]), "=r"(r[2]), "=r"(r[3]) : "r"(a));
}
__device__ __forceinline__ void ldsm4t(uint32_t* r, uint32_t a) {
    asm volatile("ldmatrix.sync.aligned.m8n8.x4.trans.shared.b16 {%0,%1,%2,%3}, [%4];"
                 : "=r"(r[0]), "=r"(r[1]), "=r"(r[2]), "=r"(r[3]) : "r"(a));
}
__device__ __forceinline__ void mma_bf16(float* d, const uint32_t* a, const uint32_t* b) {
    asm volatile("mma.sync.aligned.m16n8k16.row.col.f32.bf16.bf16.f32 "
                 "{%0,%1,%2,%3}, {%4,%5,%6,%7}, {%8,%9}, {%0,%1,%2,%3};"
                 : "+f"(d[0]), "+f"(d[1]), "+f"(d[2]), "+f"(d[3])
                 : "r"(a[0]), "r"(a[1]), "r"(a[2]), "r"(a[3]), "r"(b[0]), "r"(b[1]));
}
__device__ __forceinline__ uint32_t packbf(float lo, float hi) {
    uint32_t r;
    asm("cvt.rn.bf16x2.f32 %0, %1, %2;" : "=r"(r) : "f"(hi), "f"(lo));
    return r;
}
__device__ __forceinline__ float hi_trunc(float x) {
    return __uint_as_float(__float_as_uint(x) & 0xffff0000u);
}

// ---------------------------------------------------------------------------
// Prep: fp32 -> bf16 hi/lo (trunc hi, rn lo).
// ---------------------------------------------------------------------------
__global__ __launch_bounds__(256) void split_fp32(
    const float* __restrict__ x, __nv_bfloat16* __restrict__ h,
    __nv_bfloat16* __restrict__ l, int n4)
{
    int i = blockIdx.x * 256 + threadIdx.x;
    if (i >= n4) return;
    float4 v = ((const float4*)x)[i];
    uint32_t u0 = __float_as_uint(v.x), u1 = __float_as_uint(v.y);
    uint32_t u2 = __float_as_uint(v.z), u3 = __float_as_uint(v.w);
    uint32_t* hp = (uint32_t*)h;
    uint32_t* lp = (uint32_t*)l;
    hp[2 * i]     = (u1 & 0xffff0000u) | (u0 >> 16);
    hp[2 * i + 1] = (u3 & 0xffff0000u) | (u2 >> 16);
    lp[2 * i]     = packbf(v.x - hi_trunc(v.x), v.y - hi_trunc(v.y));
    lp[2 * i + 1] = packbf(v.z - hi_trunc(v.z), v.w - hi_trunc(v.w));
}

// ---------------------------------------------------------------------------
// Prep: W[K,N] fp32 -> Bt[N,K] bf16 hi/lo (transpose + split).
// ---------------------------------------------------------------------------
__global__ __launch_bounds__(256) void transpose_split(
    const float* __restrict__ W, __nv_bfloat16* __restrict__ bh,
    __nv_bfloat16* __restrict__ bl, int K, int N)
{
    __shared__ float t[32][33];
    const int bx = blockIdx.x * 32, by = blockIdx.y * 32;
    const int tx = threadIdx.x & 31, ty = threadIdx.x >> 5;
#pragma unroll
    for (int i = 0; i < 32; i += 8)
        t[ty + i][tx] = W[(size_t)(by + ty + i) * N + bx + tx];
    __syncthreads();
    uint16_t* bhp = (uint16_t*)bh;
#pragma unroll
    for (int i = 0; i < 32; i += 8) {
        float v = t[tx][ty + i];
        int n = bx + ty + i, k = by + tx;
        bhp[(size_t)n * K + k] = (uint16_t)(__float_as_uint(v) >> 16);
        bl[(size_t)n * K + k] = __float2bfloat16(v - hi_trunc(v));
    }
}

// ---------------------------------------------------------------------------
// mma.sync bf16x3 GEMM: 128x128 tile, Kc=32, 8 warps (2x4), warp 64x32,
// 3-stage cp.async pipeline.  Swizzle: off(r,c16) = r*64 + ((c16^((r>>1)&3))<<4)
// Term-major mma ordering: 8 independent accumulators between RAW reuses.
// ---------------------------------------------------------------------------
#define GM_MAT    8192                 // 128 rows * 64B
#define GM_STAGE  (4 * GM_MAT)         // Ah,Al,Bh,Bl = 32KB
#define GM_SMEM   (3 * GM_STAGE)       // 98304

template<bool SPLIT_OUT, bool BIAS>
__global__ __launch_bounds__(256, 2) void gemm_mma(
    const __nv_bfloat16* __restrict__ Ah, const __nv_bfloat16* __restrict__ Al,
    const __nv_bfloat16* __restrict__ Bh, const __nv_bfloat16* __restrict__ Bl,
    const float* __restrict__ bias, float* __restrict__ Cf,
    __nv_bfloat16* __restrict__ Ch, __nv_bfloat16* __restrict__ Cl,
    int Ntot, int K)
{
    extern __shared__ __align__(16) char sm[];
    const uint32_t sb = smem_u32(sm);
    const int tid = threadIdx.x, lane = tid & 31, wid = tid >> 5;
    const int wm = wid >> 2, wn = wid & 3;
    const int row0 = blockIdx.y * 128, col0 = blockIdx.x * 128;
    const int NC = K >> 5;

    float acc[4][4][4];
#pragma unroll
    for (int a = 0; a < 4; a++)
#pragma unroll
        for (int bq = 0; bq < 4; bq++)
#pragma unroll
            for (int e = 0; e < 4; e++) acc[a][bq][e] = 0.0f;

    auto load_chunk = [&](int buf, int kc) {
        const uint32_t base = sb + buf * GM_STAGE;
#pragma unroll
        for (int i = 0; i < 8; i++) {
            int u = i * 256 + tid;                 // 0..2047
            int mat = u >> 9;
            int v = u & 511, r = v >> 2, c = v & 3;
            uint32_t so = base + mat * GM_MAT + r * 64 + ((c ^ ((r >> 1) & 3)) << 4);
            const __nv_bfloat16* src = (mat == 0) ? Ah : (mat == 1) ? Al
                                     : (mat == 2) ? Bh : Bl;
            int grow = ((mat < 2) ? row0 : col0) + r;
            cp16(so, src + (size_t)grow * K + kc * 32 + c * 8);
        }
        CP_COMMIT();
    };

    load_chunk(0, 0);
    load_chunk(1, 1);

    int buf = 0;
    for (int c = 0; c < NC; c++) {
        if (c + 2 < NC) load_chunk((buf + 2) % 3, c + 2);
        const int rem = NC - 1 - c;
        if (rem >= 2)      CP_WAIT2();
        else if (rem == 1) CP_WAIT1();
        else               CP_WAIT0();
        __syncthreads();

        const uint32_t bA  = sb + buf * GM_STAGE;
        const uint32_t bAl = bA + GM_MAT;
        const uint32_t bB  = bA + 2 * GM_MAT;
        const uint32_t bBl = bA + 3 * GM_MAT;
#pragma unroll
        for (int ks = 0; ks < 2; ks++) {
            uint32_t fa[4][4], fal[4][4];
#pragma unroll
            for (int mi = 0; mi < 4; mi++) {
                int ar = wm * 64 + mi * 16 + (lane & 15);
                int ac = 2 * ks + (lane >> 4);
                uint32_t ao = (uint32_t)(ar * 64 + ((ac ^ ((ar >> 1) & 3)) << 4));
                ldsm4(fa[mi],  bA  + ao);
                ldsm4(fal[mi], bAl + ao);
            }
            const int bg = lane >> 3;
            const int br_base = wn * 32 + (bg >> 1) * 8 + (lane & 7);
            const int bc = 2 * ks + (bg & 1);
#pragma unroll
            for (int nj2 = 0; nj2 < 2; nj2++) {
                int br = br_base + nj2 * 16;
                uint32_t bo = (uint32_t)(br * 64 + ((bc ^ ((br >> 1) & 3)) << 4));
                uint32_t fb[4], fbl[4];
                ldsm4(fb,  bB  + bo);
                ldsm4(fbl, bBl + bo);
                // term-major: 8 independent mmas between accumulator reuses
#pragma unroll
                for (int half = 0; half < 2; half++)
#pragma unroll
                    for (int mi = 0; mi < 4; mi++)
                        mma_bf16(acc[mi][2 * nj2 + half], fa[mi], fb + 2 * half);
#pragma unroll
                for (int half = 0; half < 2; half++)
#pragma unroll
                    for (int mi = 0; mi < 4; mi++)
                        mma_bf16(acc[mi][2 * nj2 + half], fa[mi], fbl + 2 * half);
#pragma unroll
                for (int half = 0; half < 2; half++)
#pragma unroll
                    for (int mi = 0; mi < 4; mi++)
                        mma_bf16(acc[mi][2 * nj2 + half], fal[mi], fb + 2 * half);
            }
        }
        __syncthreads();
        buf = (buf + 1) % 3;
    }

    // -------- epilogue --------
    const int g = lane >> 2, tig = lane & 3;
#pragma unroll
    for (int mi = 0; mi < 4; mi++) {
#pragma unroll
        for (int nj = 0; nj < 4; nj++) {
            int row = row0 + wm * 64 + mi * 16 + g;
            int col = col0 + wn * 32 + nj * 8 + tig * 2;
            float c0 = acc[mi][nj][0], c1 = acc[mi][nj][1];
            float c2 = acc[mi][nj][2], c3 = acc[mi][nj][3];
            if (SPLIT_OUT) {
                uint32_t u0 = __float_as_uint(c0), u1 = __float_as_uint(c1);
                uint32_t u2 = __float_as_uint(c2), u3 = __float_as_uint(c3);
                *(uint32_t*)(Ch + (size_t)row * Ntot + col) =
                    (u1 & 0xffff0000u) | (u0 >> 16);
                *(uint32_t*)(Cl + (size_t)row * Ntot + col) =
                    packbf(c0 - hi_trunc(c0), c1 - hi_trunc(c1));
                *(uint32_t*)(Ch + (size_t)(row + 8) * Ntot + col) =
                    (u3 & 0xffff0000u) | (u2 >> 16);
                *(uint32_t*)(Cl + (size_t)(row + 8) * Ntot + col) =
                    packbf(c2 - hi_trunc(c2), c3 - hi_trunc(c3));
            } else {
                float b0 = BIAS ? bias[col] : 0.0f;
                float b1 = BIAS ? bias[col + 1] : 0.0f;
                float2 v0; v0.x = c0 + b0; v0.y = c1 + b1;
                float2 v1; v1.x = c2 + b0; v1.y = c3 + b1;
                *(float2*)(Cf + (size_t)row * Ntot + col) = v0;
                *(float2*)(Cf + (size_t)(row + 8) * Ntot + col) = v1;
            }
        }
    }
}

// ---------------------------------------------------------------------------
// ReLU attention, mma bf16x3.  Block = (b, h, 128 q-rows), 8 warps.
// K/V 64-row tiles double-buffered.  All 8 nj K/V frags batched into regs,
// then term-major mma bursts (8 independent accumulators between reuses).
// Swizzle off(r,c16)=r*128+((c^(r&7))<<4)
// ---------------------------------------------------------------------------
#define ATQ_MAT   16384                // 128 rows * 128B
#define ATKV_MAT  8192                 // 64 rows * 128B
#define AT_STAGE  (4 * ATKV_MAT)       // Kh,Kl,Vh,Vl = 32KB
#define AT_SMEM   (2 * ATQ_MAT + 2 * AT_STAGE)   // 98304

__global__ __launch_bounds__(256, 2) void attn_mma(
    const __nv_bfloat16* __restrict__ qh, const __nv_bfloat16* __restrict__ ql,
    float* __restrict__ o)
{
    extern __shared__ __align__(16) char sm[];
    const uint32_t sb = smem_u32(sm);
    const uint32_t sQh = sb, sQl = sb + ATQ_MAT;
    const uint32_t sKV = sb + 2 * ATQ_MAT;
    const int qt = (int)gridDim.x - 1 - (int)blockIdx.x;   // heavy first
    const int h = blockIdx.y, b = blockIdx.z;
    const int tid = threadIdx.x, lane = tid & 31, wid = tid >> 5;
    const int g = lane >> 2, tig = lane & 3;
    const int KT = 2 * (qt + 1);

    // ---- Q tile loads (128 x 64 bf16 hi/lo) : group 0 ----
#pragma unroll
    for (int i = 0; i < 4; i++) {
        int u = i * 256 + tid;             // 0..1023
        int r = u >> 3, c = u & 7;
        uint32_t so = (uint32_t)(r * 128 + ((c ^ (r & 7)) << 4));
        size_t go = (size_t)(b * S_ + qt * 128 + r) * TD + h * 64 + c * 8;
        cp16(sQh + so, qh + go);
        cp16(sQl + so, ql + go);
    }
    CP_COMMIT();

    auto load_kv = [&](int buf, int kt) {
        const uint32_t base = sKV + buf * AT_STAGE;
#pragma unroll
        for (int i = 0; i < 8; i++) {
            int u = i * 256 + tid;         // 0..2047
            int mat = u >> 9;              // 0 Kh, 1 Kl, 2 Vh, 3 Vl
            int v = u & 511, r = v >> 3, c = v & 7;
            uint32_t so = base + mat * ATKV_MAT +
                          (uint32_t)(r * 128 + ((c ^ (r & 7)) << 4));
            size_t grow = (size_t)(b * S_ + kt * 64 + r);
            int gcol = ((mat < 2) ? D_ : 2 * D_) + h * 64 + c * 8;
            const __nv_bfloat16* src = (mat & 1) ? ql : qh;
            cp16(so, src + grow * TD + gcol);
        }
        CP_COMMIT();
    };

    load_kv(0, 0);           // group 1

    float accO[8][4];
#pragma unroll
    for (int nj = 0; nj < 8; nj++)
#pragma unroll
        for (int e = 0; e < 4; e++) accO[nj][e] = 0.0f;

    const int rw_lo = qt * 128 + wid * 16;       // warp's first abs q row

    for (int kt = 0; kt < KT; kt++) {
        if (kt + 1 < KT) { load_kv((kt + 1) & 1, kt + 1); CP_WAIT1(); }
        else             { CP_WAIT0(); }
        __syncthreads();

        const bool skip = (kt * 64 > rw_lo + 15);
        if (!skip) {
            const uint32_t bK = sKV + (kt & 1) * AT_STAGE;
            const uint32_t sKh = bK, sKl = bK + ATKV_MAT;
            const uint32_t sVh = bK + 2 * ATKV_MAT, sVl = bK + 3 * ATKV_MAT;

            // ---- S = Q @ K^T  (16 x 64 per warp) ----
            float accS[8][4];
#pragma unroll
            for (int nj = 0; nj < 8; nj++)
#pragma unroll
                for (int e = 0; e < 4; e++) accS[nj][e] = 0.0f;

            const int kg = lane >> 3;                 // 0..3
            const int kr_base = (kg >> 1) * 8 + (lane & 7);
#pragma unroll
            for (int ks = 0; ks < 4; ks++) {
                int qr = wid * 16 + (lane & 15);
                int qc = 2 * ks + (lane >> 4);
                uint32_t ao = (uint32_t)(qr * 128 + ((qc ^ (qr & 7)) << 4));
                uint32_t fqh[4], fql[4];
                ldsm4(fqh, sQh + ao);
                ldsm4(fql, sQl + ao);
                const int kc = 2 * ks + (kg & 1);
                uint32_t fkh[4][4], fkl[4][4];
#pragma unroll
                for (int nj2 = 0; nj2 < 4; nj2++) {
                    int kr = nj2 * 16 + kr_base;
                    uint32_t bo = (uint32_t)(kr * 128 + ((kc ^ (kr & 7)) << 4));
                    ldsm4(fkh[nj2], sKh + bo);
                    ldsm4(fkl[nj2], sKl + bo);
                }
                // term-major bursts: 8 independent accs between reuses
#pragma unroll
                for (int nj = 0; nj < 8; nj++)
                    mma_bf16(accS[nj], fqh, fkh[nj >> 1] + 2 * (nj & 1));
#pragma unroll
                for (int nj = 0; nj < 8; nj++)
                    mma_bf16(accS[nj], fqh, fkl[nj >> 1] + 2 * (nj & 1));
#pragma unroll
                for (int nj = 0; nj < 8; nj++)
                    mma_bf16(accS[nj], fql, fkh[nj >> 1] + 2 * (nj & 1));
            }

            // ---- scale, relu, causal mask, split to bf16 A-frags ----
            const bool needmask = (kt * 64 + 63 > rw_lo);
            uint32_t sh[4][4], sl[4][4];
#pragma unroll
            for (int f = 0; f < 4; f++) {
#pragma unroll
                for (int half = 0; half < 2; half++) {
                    const int nj = 2 * f + half;
                    float s[4];
#pragma unroll
                    for (int e = 0; e < 4; e++) {
                        float v = accS[nj][e] * 0.125f;
                        v = fmaxf(v, 0.0f);
                        if (needmask) {
                            int qa = rw_lo + g + ((e & 2) ? 8 : 0);
                            int ka = kt * 64 + nj * 8 + tig * 2 + (e & 1);
                            if (ka > qa) v = 0.0f;
                        }
                        s[e] = v;
                    }
                    uint32_t u0 = __float_as_uint(s[0]), u1 = __float_as_uint(s[1]);
                    uint32_t u2 = __float_as_uint(s[2]), u3 = __float_as_uint(s[3]);
                    sh[f][half * 2 + 0] = (u1 & 0xffff0000u) | (u0 >> 16);
                    sh[f][half * 2 + 1] = (u3 & 0xffff0000u) | (u2 >> 16);
                    sl[f][half * 2 + 0] = packbf(s[0] - hi_trunc(s[0]), s[1] - hi_trunc(s[1]));
                    sl[f][half * 2 + 1] = packbf(s[2] - hi_trunc(s[2]), s[3] - hi_trunc(s[3]));
                }
            }

            // ---- O += S @ V  (V frags batched, term-major bursts) ----
#pragma unroll
            for (int ks = 0; ks < 4; ks++) {
                int vr = ks * 16 + ((lane >> 3) & 1) * 8 + (lane & 7);
                uint32_t vrow = (uint32_t)(vr * 128);
                uint32_t vsw = (uint32_t)(vr & 7);
                const int vcg = lane >> 4;            // col within pair
                uint32_t fvh[4][4], fvl[4][4];
#pragma unroll
                for (int nj2 = 0; nj2 < 4; nj2++) {
                    uint32_t co = (uint32_t)(((uint32_t)(2 * nj2 + vcg) ^ vsw) << 4);
                    ldsm4t(fvh[nj2], sVh + vrow + co);
                    ldsm4t(fvl[nj2], sVl + vrow + co);
                }
#pragma unroll
                for (int nj = 0; nj < 8; nj++)
                    mma_bf16(accO[nj], sh[ks], fvh[nj >> 1] + 2 * (nj & 1));
#pragma unroll
                for (int nj = 0; nj < 8; nj++)
                    mma_bf16(accO[nj], sh[ks], fvl[nj >> 1] + 2 * (nj & 1));
#pragma unroll
                for (int nj = 0; nj < 8; nj++)
                    mma_bf16(accO[nj], sl[ks], fvh[nj >> 1] + 2 * (nj & 1));
            }
        }
        __syncthreads();
    }

    // ---- store O (fp32) ----
#pragma unroll
    for (int nj = 0; nj < 8; nj++) {
        int col = h * 64 + nj * 8 + tig * 2;
        size_t row = (size_t)(b * S_ + qt * 128 + wid * 16 + g);
        float2 v0; v0.x = accO[nj][0]; v0.y = accO[nj][1];
        float2 v1; v1.x = accO[nj][2]; v1.y = accO[nj][3];
        *(float2*)(o + row * D_ + col) = v0;
        *(float2*)(o + (row + 8) * D_ + col) = v1;
    }
}

// ---------------------------------------------------------------------------
// Gated RMSNorm; reads o fp32, writes bf16 hi/lo split (A operand of GEMM2).
// ---------------------------------------------------------------------------
__global__ __launch_bounds__(256) void rms_gate_split(
    const float* __restrict__ o, const float* __restrict__ scale,
    const float* __restrict__ gate, __nv_bfloat16* __restrict__ ah,
    __nv_bfloat16* __restrict__ al)
{
    const int row = blockIdx.x;
    const int tid = threadIdx.x;
    const float* p = o + (size_t)row * D_;

    float4 x = ((const float4*)p)[tid];
    float ss = x.x * x.x + x.y * x.y + x.z * x.z + x.w * x.w;
#pragma unroll
    for (int off = 16; off; off >>= 1)
        ss += __shfl_xor_sync(0xffffffffu, ss, off);

    __shared__ float red[8];
    __shared__ float s_inv;
    if ((tid & 31) == 0) red[tid >> 5] = ss;
    __syncthreads();
    if (tid == 0) {
        float t = 0.0f;
#pragma unroll
        for (int i = 0; i < 8; i++) t += red[i];
        s_inv = rsqrtf(t * (1.0f / (float)D_) + 1e-7f);
    }
    __syncthreads();
    const float inv = s_inv;

    float4 sc = ((const float4*)scale)[tid];
    float4 gv = ((const float4*)gate)[tid];
    float r0 = sc.x * x.x * inv * (1.0f / (1.0f + expf(-gv.x * x.x)));
    float r1 = sc.y * x.y * inv * (1.0f / (1.0f + expf(-gv.y * x.y)));
    float r2 = sc.z * x.z * inv * (1.0f / (1.0f + expf(-gv.z * x.z)));
    float r3 = sc.w * x.w * inv * (1.0f / (1.0f + expf(-gv.w * x.w)));

    uint32_t u0 = __float_as_uint(r0), u1 = __float_as_uint(r1);
    uint32_t u2 = __float_as_uint(r2), u3 = __float_as_uint(r3);
    uint32_t* hp = (uint32_t*)ah;
    uint32_t* lp = (uint32_t*)al;
    const size_t base = (size_t)row * (D_ / 2) + tid * 2;
    hp[base]     = (u1 & 0xffff0000u) | (u0 >> 16);
    hp[base + 1] = (u3 & 0xffff0000u) | (u2 >> 16);
    lp[base]     = packbf(r0 - hi_trunc(r0), r1 - hi_trunc(r1));
    lp[base + 1] = packbf(r2 - hi_trunc(r2), r3 - hi_trunc(r3));
}

// ---------------------------------------------------------------------------
extern "C" void kernel_launch(void* const* d_in, const int* in_sizes, int n_in,
                              void* d_out, int out_size)
{
    const float* x     = (const float*)d_in[0];
    // d_in[1] mem_mask: causal by construction; mask*0 then relu == skip. Unused.
    const float* Wqkv  = (const float*)d_in[2];
    const float* W_out = (const float*)d_in[3];
    const float* b_out = (const float*)d_in[4];
    const float* scale = (const float*)d_in[5];
    const float* gate  = (const float*)d_in[6];
    float* out = (float*)d_out;

    float* obuf;
    __nv_bfloat16 *qkvh, *qkvl, *ah, *al, *bh, *bl;
    cudaGetSymbolAddress((void**)&obuf, g_o);
    cudaGetSymbolAddress((void**)&qkvh, g_qkvh);
    cudaGetSymbolAddress((void**)&qkvl, g_qkvl);
    cudaGetSymbolAddress((void**)&ah, g_ah);
    cudaGetSymbolAddress((void**)&al, g_al);
    cudaGetSymbolAddress((void**)&bh, g_bh);
    cudaGetSymbolAddress((void**)&bl, g_bl);

    cudaFuncSetAttribute(gemm_mma<true, false>,
                         cudaFuncAttributeMaxDynamicSharedMemorySize, GM_SMEM);
    cudaFuncSetAttribute(gemm_mma<false, true>,
                         cudaFuncAttributeMaxDynamicSharedMemorySize, GM_SMEM);
    cudaFuncSetAttribute(attn_mma,
                         cudaFuncAttributeMaxDynamicSharedMemorySize, AT_SMEM);

    // 1) split x (A of GEMM1); transpose+split Wqkv
    split_fp32<<<(ROWS * D_ / 4 + 255) / 256, 256>>>(x, ah, al, ROWS * D_ / 4);
    transpose_split<<<dim3(TD / 32, D_ / 32), 256>>>(Wqkv, bh, bl, D_, TD);

    // 2) qkv = x @ Wqkv  -> bf16 hi/lo directly (fused split)
    gemm_mma<true, false><<<dim3(TD / 128, ROWS / 128), 256, GM_SMEM>>>(
        ah, al, bh, bl, nullptr, nullptr, qkvh, qkvl, TD, D_);

    // 3) causal ReLU attention (term-major mma ordering)
    attn_mma<<<dim3(S_ / 128, H_, B_), 256, AT_SMEM>>>(qkvh, qkvl, obuf);

    // 4) gated RMSNorm -> split (A of GEMM2)
    rms_gate_split<<<ROWS, 256>>>(obuf, scale, gate, ah, al);

    // 5) out = o @ W_out + b_out
    transpose_split<<<dim3(D_ / 32, D_ / 32), 256>>>(W_out, bh, bl, D_, D_);
    gemm_mma<false, true><<<dim3(D_ / 128, ROWS / 128), 256, GM_SMEM>>>(
        ah, al, bh, bl, b_out, out, nullptr, nullptr, D_, D_);
}